// round 1
// baseline (speedup 1.0000x reference)
#include <cuda_runtime.h>
#include <math.h>
#include <stdint.h>

#define NN 50000
#define NE 800000
#define LIN 1024
#define DH 256

// ---------------- scratch (static device globals; no allocation) ----------------
__device__ float g_Q[(size_t)NN * DH];
__device__ float g_K[(size_t)NN * DH];
__device__ float g_V[(size_t)NN * DH];
__device__ float g_S[(size_t)NN * DH];
__device__ float g_TA[(size_t)NN * DH];   // h@Wa + ba (pre-tanh)
__device__ float g_TB[(size_t)NN * DH];   // h@Wb + bb (pre-sigmoid)
__device__ float g_alpha[NE];
__device__ int   g_srcSorted[NE];
__device__ int   g_deg[NN];
__device__ int   g_off[NN + 1];
__device__ int   g_cur[NN];
__device__ float g_scores[NN * 2];
__device__ float g_cmax[2];
__device__ float g_csum[2];

__device__ __forceinline__ float* out_sel(int s) {
    switch (s) {
        case 0: return g_Q;
        case 1: return g_K;
        case 2: return g_V;
        case 3: return g_S;
        case 4: return g_TA;
        default: return g_TB;
    }
}

__device__ __forceinline__ float gelu_exact(float x) {
    return 0.5f * x * (1.0f + erff(x * 0.70710678118654752440f));
}

// ---------------- init ----------------
__global__ void init_kernel(float* __restrict__ out) {
    int i = blockIdx.x * blockDim.x + threadIdx.x;
    if (i < NN) g_deg[i] = 0;
    if (i < 512) out[i] = 0.0f;   // y accumulators
}

// ---------------- CSR build ----------------
__global__ void count_kernel(const int* __restrict__ ei) {
    int e = blockIdx.x * blockDim.x + threadIdx.x;
    if (e < NE) atomicAdd(&g_deg[ei[NE + e]], 1);
}

__global__ void scan_kernel() {
    __shared__ int sh[1024];
    __shared__ int carry;
    int tid = threadIdx.x;
    if (tid == 0) carry = 0;
    __syncthreads();
    for (int base = 0; base < NN; base += 1024) {
        int idx = base + tid;
        int v = (idx < NN) ? g_deg[idx] : 0;
        sh[tid] = v;
        __syncthreads();
        #pragma unroll
        for (int o = 1; o < 1024; o <<= 1) {
            int t = (tid >= o) ? sh[tid - o] : 0;
            __syncthreads();
            sh[tid] += t;
            __syncthreads();
        }
        int excl = sh[tid] - v + carry;
        if (idx < NN) { g_off[idx] = excl; g_cur[idx] = excl; }
        int total = sh[1023];
        __syncthreads();
        if (tid == 0) carry += total;
        __syncthreads();
    }
    if (tid == 0) g_off[NN] = carry;
}

__global__ void scatter_kernel(const int* __restrict__ ei) {
    int e = blockIdx.x * blockDim.x + threadIdx.x;
    if (e < NE) {
        int d = ei[NE + e];
        int p = atomicAdd(&g_cur[d], 1);
        g_srcSorted[p] = ei[e];
    }
}

// ---------------- SGEMM: X[M,K] @ Wmat[K,256] + bias -> out_sel buffers ----------
// blockIdx.x selects (matrix, 128-col half); blockIdx.y is the 128-row tile.
template <int KDIM>
__global__ __launch_bounds__(256, 2)
void sgemm_multi(const float* __restrict__ X,
                 const float* __restrict__ W0, const float* __restrict__ W1,
                 const float* __restrict__ W2, const float* __restrict__ W3,
                 const float* __restrict__ c0, const float* __restrict__ c1,
                 const float* __restrict__ c2, const float* __restrict__ c3,
                 int M, int outSelBase) {
    constexpr int BK = 16;
    __shared__ float As[2][BK][132];
    __shared__ float Bs[2][BK][128];

    int mat = blockIdx.x >> 1;
    int ncol0 = (blockIdx.x & 1) * 128;
    const float* W = (mat == 0) ? W0 : (mat == 1) ? W1 : (mat == 2) ? W2 : W3;
    const float* bias = (mat == 0) ? c0 : (mat == 1) ? c1 : (mat == 2) ? c2 : c3;
    float* O = out_sel(outSelBase + mat);

    int m0 = blockIdx.y * 128;
    int tid = threadIdx.x;
    int tx = tid & 15, ty = tid >> 4;

    int aRow = tid >> 2;        // 0..63
    int aCol = (tid & 3) * 4;   // 0,4,8,12
    int bRow = tid >> 5;        // 0..7
    int bCol = (tid & 31) * 4;  // 0..124

    float acc[8][8];
    #pragma unroll
    for (int i = 0; i < 8; i++)
        #pragma unroll
        for (int j = 0; j < 8; j++) acc[i][j] = 0.0f;

    float4 ra0, ra1, rb0, rb1;
    const float4 fz = make_float4(0.f, 0.f, 0.f, 0.f);

    // prologue: tile 0
    {
        int k = aCol;
        int r0 = m0 + aRow, r1 = m0 + aRow + 64;
        ra0 = (r0 < M) ? *(const float4*)(X + (size_t)r0 * KDIM + k) : fz;
        ra1 = (r1 < M) ? *(const float4*)(X + (size_t)r1 * KDIM + k) : fz;
        int kb = bRow;
        rb0 = *(const float4*)(W + (size_t)kb * 256 + ncol0 + bCol);
        rb1 = *(const float4*)(W + (size_t)(kb + 8) * 256 + ncol0 + bCol);
        As[0][aCol + 0][aRow] = ra0.x; As[0][aCol + 1][aRow] = ra0.y;
        As[0][aCol + 2][aRow] = ra0.z; As[0][aCol + 3][aRow] = ra0.w;
        As[0][aCol + 0][aRow + 64] = ra1.x; As[0][aCol + 1][aRow + 64] = ra1.y;
        As[0][aCol + 2][aRow + 64] = ra1.z; As[0][aCol + 3][aRow + 64] = ra1.w;
        *(float4*)&Bs[0][bRow][bCol] = rb0;
        *(float4*)&Bs[0][bRow + 8][bCol] = rb1;
    }
    __syncthreads();

    constexpr int T = KDIM / BK;
    for (int t = 0; t < T; ++t) {
        int cur = t & 1;
        if (t + 1 < T) {
            int k = (t + 1) * BK + aCol;
            int r0 = m0 + aRow, r1 = m0 + aRow + 64;
            ra0 = (r0 < M) ? *(const float4*)(X + (size_t)r0 * KDIM + k) : fz;
            ra1 = (r1 < M) ? *(const float4*)(X + (size_t)r1 * KDIM + k) : fz;
            int kb = (t + 1) * BK + bRow;
            rb0 = *(const float4*)(W + (size_t)kb * 256 + ncol0 + bCol);
            rb1 = *(const float4*)(W + (size_t)(kb + 8) * 256 + ncol0 + bCol);
        }
        #pragma unroll
        for (int k = 0; k < BK; k++) {
            float4 a0 = *(const float4*)&As[cur][k][ty * 4];
            float4 a1 = *(const float4*)&As[cur][k][64 + ty * 4];
            float4 b0 = *(const float4*)&Bs[cur][k][tx * 4];
            float4 b1 = *(const float4*)&Bs[cur][k][64 + tx * 4];
            float av[8] = {a0.x, a0.y, a0.z, a0.w, a1.x, a1.y, a1.z, a1.w};
            float bv[8] = {b0.x, b0.y, b0.z, b0.w, b1.x, b1.y, b1.z, b1.w};
            #pragma unroll
            for (int i = 0; i < 8; i++)
                #pragma unroll
                for (int j = 0; j < 8; j++) acc[i][j] += av[i] * bv[j];
        }
        if (t + 1 < T) {
            int nxt = (t + 1) & 1;
            As[nxt][aCol + 0][aRow] = ra0.x; As[nxt][aCol + 1][aRow] = ra0.y;
            As[nxt][aCol + 2][aRow] = ra0.z; As[nxt][aCol + 3][aRow] = ra0.w;
            As[nxt][aCol + 0][aRow + 64] = ra1.x; As[nxt][aCol + 1][aRow + 64] = ra1.y;
            As[nxt][aCol + 2][aRow + 64] = ra1.z; As[nxt][aCol + 3][aRow + 64] = ra1.w;
            *(float4*)&Bs[nxt][bRow][bCol] = rb0;
            *(float4*)&Bs[nxt][bRow + 8][bCol] = rb1;
            __syncthreads();
        }
    }

    // epilogue: bias + store
    #pragma unroll
    for (int i = 0; i < 8; i++) {
        int r = m0 + ((i < 4) ? (ty * 4 + i) : (64 + ty * 4 + i - 4));
        if (r < M) {
            #pragma unroll
            for (int jj = 0; jj < 2; jj++) {
                int c = ncol0 + jj * 64 + tx * 4;
                float4 v;
                v.x = acc[i][jj * 4 + 0] + bias[c + 0];
                v.y = acc[i][jj * 4 + 1] + bias[c + 1];
                v.z = acc[i][jj * 4 + 2] + bias[c + 2];
                v.w = acc[i][jj * 4 + 3] + bias[c + 3];
                *(float4*)(O + (size_t)r * 256 + c) = v;
            }
        }
    }
}

// ---------------- fused edge softmax + aggregation + residual + gelu --------------
__global__ __launch_bounds__(256)
void attn_kernel(float* __restrict__ hOut) {
    int warp = (blockIdx.x * blockDim.x + threadIdx.x) >> 5;
    int lane = threadIdx.x & 31;
    if (warp >= NN) return;
    int d = warp;

    const float4* Qr = (const float4*)(g_Q + (size_t)d * 256);
    float4 q0 = Qr[lane], q1 = Qr[lane + 32];
    int e0 = g_off[d], e1 = g_off[d + 1];

    float amax = -INFINITY;
    for (int e = e0; e < e1; ++e) {
        int s = g_srcSorted[e];
        const float4* Kr = (const float4*)(g_K + (size_t)s * 256);
        float4 k0 = Kr[lane], k1 = Kr[lane + 32];
        float dot = q0.x * k0.x + q0.y * k0.y + q0.z * k0.z + q0.w * k0.w
                  + q1.x * k1.x + q1.y * k1.y + q1.z * k1.z + q1.w * k1.w;
        #pragma unroll
        for (int o = 16; o; o >>= 1) dot += __shfl_xor_sync(0xffffffffu, dot, o);
        dot *= 0.0625f;           // 1/sqrt(256)
        g_alpha[e] = dot;         // every lane stores same value (own-store/own-load)
        amax = fmaxf(amax, dot);
    }

    float den = 0.0f;
    float4 acc0 = make_float4(0, 0, 0, 0), acc1 = make_float4(0, 0, 0, 0);
    for (int e = e0; e < e1; ++e) {
        float w = expf(g_alpha[e] - amax);
        den += w;
        int s = g_srcSorted[e];
        const float4* Vr = (const float4*)(g_V + (size_t)s * 256);
        float4 v0 = Vr[lane], v1 = Vr[lane + 32];
        acc0.x += w * v0.x; acc0.y += w * v0.y; acc0.z += w * v0.z; acc0.w += w * v0.w;
        acc1.x += w * v1.x; acc1.y += w * v1.y; acc1.z += w * v1.z; acc1.w += w * v1.w;
    }
    float inv = 1.0f / (den + 1e-16f);

    const float4* Sr = (const float4*)(g_S + (size_t)d * 256);
    float4 s0 = Sr[lane], s1 = Sr[lane + 32];
    float4 h0, h1;
    h0.x = gelu_exact(acc0.x * inv + s0.x);
    h0.y = gelu_exact(acc0.y * inv + s0.y);
    h0.z = gelu_exact(acc0.z * inv + s0.z);
    h0.w = gelu_exact(acc0.w * inv + s0.w);
    h1.x = gelu_exact(acc1.x * inv + s1.x);
    h1.y = gelu_exact(acc1.y * inv + s1.y);
    h1.z = gelu_exact(acc1.z * inv + s1.z);
    h1.w = gelu_exact(acc1.w * inv + s1.w);

    float4* Hr = (float4*)(hOut + (size_t)d * 256);
    Hr[lane] = h0;
    Hr[lane + 32] = h1;
}

// ---------------- tanh*sigmoid gate + scores (g @ Wc + bc) -----------------------
__global__ __launch_bounds__(256)
void act_scores_kernel(const float* __restrict__ Wc, const float* __restrict__ bc) {
    int warp = (blockIdx.x * blockDim.x + threadIdx.x) >> 5;
    int lane = threadIdx.x & 31;
    if (warp >= NN) return;
    int n = warp;

    const float4* Ar = (const float4*)(g_TA + (size_t)n * 256);
    const float4* Br = (const float4*)(g_TB + (size_t)n * 256);
    float s0 = 0.0f, s1 = 0.0f;
    #pragma unroll
    for (int part = 0; part < 2; part++) {
        int idx = lane + part * 32;
        float4 av = Ar[idx], bv = Br[idx];
        float aa[4] = {av.x, av.y, av.z, av.w};
        float bb[4] = {bv.x, bv.y, bv.z, bv.w};
        int jbase = idx * 4;
        #pragma unroll
        for (int u = 0; u < 4; u++) {
            float a = tanhf(aa[u]);
            float b = 1.0f / (1.0f + expf(-bb[u]));
            float g = a * b;
            s0 += g * Wc[(jbase + u) * 2 + 0];
            s1 += g * Wc[(jbase + u) * 2 + 1];
        }
    }
    #pragma unroll
    for (int o = 16; o; o >>= 1) {
        s0 += __shfl_xor_sync(0xffffffffu, s0, o);
        s1 += __shfl_xor_sync(0xffffffffu, s1, o);
    }
    if (lane == 0) {
        g_scores[2 * n + 0] = s0 + bc[0];
        g_scores[2 * n + 1] = s1 + bc[1];
    }
}

// ---------------- column softmax stats over 50000 rows ---------------------------
__global__ void softmax_stats_kernel() {
    __shared__ float sh[1024];
    int tid = threadIdx.x;
    float m0 = -INFINITY, m1 = -INFINITY;
    for (int i = tid; i < NN; i += 1024) {
        m0 = fmaxf(m0, g_scores[2 * i]);
        m1 = fmaxf(m1, g_scores[2 * i + 1]);
    }
    sh[tid] = m0; __syncthreads();
    for (int o = 512; o; o >>= 1) { if (tid < o) sh[tid] = fmaxf(sh[tid], sh[tid + o]); __syncthreads(); }
    float cm0 = sh[0]; __syncthreads();
    sh[tid] = m1; __syncthreads();
    for (int o = 512; o; o >>= 1) { if (tid < o) sh[tid] = fmaxf(sh[tid], sh[tid + o]); __syncthreads(); }
    float cm1 = sh[0]; __syncthreads();

    float s0 = 0.0f, s1 = 0.0f;
    for (int i = tid; i < NN; i += 1024) {
        s0 += expf(g_scores[2 * i] - cm0);
        s1 += expf(g_scores[2 * i + 1] - cm1);
    }
    sh[tid] = s0; __syncthreads();
    for (int o = 512; o; o >>= 1) { if (tid < o) sh[tid] += sh[tid + o]; __syncthreads(); }
    float sum0 = sh[0]; __syncthreads();
    sh[tid] = s1; __syncthreads();
    for (int o = 512; o; o >>= 1) { if (tid < o) sh[tid] += sh[tid + o]; __syncthreads(); }
    float sum1 = sh[0];
    if (tid == 0) {
        g_cmax[0] = cm0; g_cmax[1] = cm1;
        g_csum[0] = sum0; g_csum[1] = sum1;
    }
}

// ---------------- attn, A output, y = attn.T @ h ---------------------------------
__global__ __launch_bounds__(256)
void output_kernel(const int* __restrict__ label,
                   const float* __restrict__ h,
                   float* __restrict__ out) {
    int t = threadIdx.x;  // column 0..255
    float cm0 = g_cmax[0], cm1 = g_cmax[1];
    float is0 = 1.0f / g_csum[0], is1 = 1.0f / g_csum[1];
    int lbl = *label;
    float y0 = 0.0f, y1 = 0.0f;
    for (int n = blockIdx.x; n < NN; n += gridDim.x) {
        float sc0 = g_scores[2 * n], sc1 = g_scores[2 * n + 1];
        float a0 = expf(sc0 - cm0) * is0;
        float a1 = expf(sc1 - cm1) * is1;
        if (t == 0) out[512 + n] = (lbl == 0) ? a0 : a1;
        float hv = h[(size_t)n * 256 + t];
        y0 += a0 * hv;
        y1 += a1 * hv;
    }
    atomicAdd(&out[t], y0);
    atomicAdd(&out[256 + t], y1);
}

// ---------------- launch ----------------
extern "C" void kernel_launch(void* const* d_in, const int* in_sizes, int n_in,
                              void* d_out, int out_size) {
    const float* x  = (const float*)d_in[0];
    const float* Wq = (const float*)d_in[1];  const float* bq = (const float*)d_in[2];
    const float* Wk = (const float*)d_in[3];  const float* bk = (const float*)d_in[4];
    const float* Wv = (const float*)d_in[5];  const float* bv = (const float*)d_in[6];
    const float* Ws = (const float*)d_in[7];  const float* bs = (const float*)d_in[8];
    const float* Wa = (const float*)d_in[9];  const float* ba = (const float*)d_in[10];
    const float* Wb = (const float*)d_in[11]; const float* bb = (const float*)d_in[12];
    const float* Wc = (const float*)d_in[13]; const float* bc = (const float*)d_in[14];
    const int*   ei = (const int*)d_in[15];
    const int*   lb = (const int*)d_in[16];

    float* out  = (float*)d_out;
    float* hOut = out + 512 + NN;   // h region: 50000 x 256

    init_kernel<<<(NN + 255) / 256, 256>>>(out);
    count_kernel<<<(NE + 255) / 256, 256>>>(ei);
    scan_kernel<<<1, 1024>>>();
    scatter_kernel<<<(NE + 255) / 256, 256>>>(ei);

    // Q|K|V|S = x @ [Wq Wk Wv Ws] + biases
    sgemm_multi<LIN><<<dim3(8, (NN + 127) / 128), 256>>>(
        x, Wq, Wk, Wv, Ws, bq, bk, bv, bs, NN, 0);

    attn_kernel<<<(NN * 32 + 255) / 256, 256>>>(hOut);

    // TA|TB = h @ [Wa Wb] + biases
    sgemm_multi<DH><<<dim3(4, (NN + 127) / 128), 256>>>(
        hOut, Wa, Wb, Wa, Wa, ba, bb, ba, ba, NN, 4);

    act_scores_kernel<<<(NN * 32 + 255) / 256, 256>>>(Wc, bc);
    softmax_stats_kernel<<<1, 1024>>>();
    output_kernel<<<512, 256>>>(lb, hOut, out);
}

// round 4
// speedup vs baseline: 1.7042x; 1.7042x over previous
#include <cuda_runtime.h>
#include <cuda_bf16.h>
#include <math.h>
#include <stdint.h>

#define NN 50000
#define NE 800000
#define LIN 1024
#define DH 256

// ===================== scratch (static device globals) =====================
__device__ float g_Q[(size_t)NN * DH];
__device__ float g_K[(size_t)NN * DH];
__device__ float g_V[(size_t)NN * DH];
__device__ float g_S[(size_t)NN * DH];
__device__ float g_TA[(size_t)NN * DH];
__device__ float g_TB[(size_t)NN * DH];
__device__ float g_alpha[NE];
__device__ int   g_srcSorted[NE];
__device__ int   g_deg[NN];
__device__ int   g_off[NN + 1];
__device__ int   g_cur[NN];
__device__ float g_scores[NN * 2];
__device__ float g_cmax[2];
__device__ float g_csum[2];

// bf16 split weights, transposed to [N=256, K] per matrix (k-major rows).
#define WBIG (256 * 1024)
#define WSML (256 * 256)
__device__ __nv_bfloat16 g_WH[4 * WBIG + 2 * WSML];
__device__ __nv_bfloat16 g_WL[4 * WBIG + 2 * WSML];

__device__ __forceinline__ float* out_sel(int s) {
    switch (s) {
        case 0: return g_Q;
        case 1: return g_K;
        case 2: return g_V;
        case 3: return g_S;
        case 4: return g_TA;
        default: return g_TB;
    }
}

__device__ __forceinline__ float gelu_exact(float x) {
    return 0.5f * x * (1.0f + erff(x * 0.70710678118654752440f));
}

__device__ __forceinline__ uint32_t smem_u32(const void* p) {
    uint32_t a;
    asm("{ .reg .u64 t; cvta.to.shared.u64 t, %1; cvt.u32.u64 %0, t; }" : "=r"(a) : "l"(p));
    return a;
}

#define LDM_X4(r0, r1, r2, r3, addr) \
    asm volatile("ldmatrix.sync.aligned.m8n8.x4.shared.b16 {%0,%1,%2,%3}, [%4];" \
                 : "=r"(r0), "=r"(r1), "=r"(r2), "=r"(r3) : "r"(addr))

#define CP16(dst, src) \
    asm volatile("cp.async.cg.shared.global [%0], [%1], 16;" :: "r"(dst), "l"(src))

__device__ __forceinline__ void mma_bf16(float* d, const uint32_t* a, const uint32_t* b) {
    asm volatile(
        "mma.sync.aligned.m16n8k16.row.col.f32.bf16.bf16.f32 "
        "{%0,%1,%2,%3},{%4,%5,%6,%7},{%8,%9},{%0,%1,%2,%3};"
        : "+f"(d[0]), "+f"(d[1]), "+f"(d[2]), "+f"(d[3])
        : "r"(a[0]), "r"(a[1]), "r"(a[2]), "r"(a[3]), "r"(b[0]), "r"(b[1]));
}

// ===================== init =====================
__global__ void init_kernel(float* __restrict__ out) {
    int i = blockIdx.x * blockDim.x + threadIdx.x;
    if (i < NN) g_deg[i] = 0;
    if (i < 512) out[i] = 0.0f;
}

// ===================== CSR build =====================
__global__ void count_kernel(const int* __restrict__ ei) {
    int e = blockIdx.x * blockDim.x + threadIdx.x;
    if (e < NE) atomicAdd(&g_deg[ei[NE + e]], 1);
}

__global__ void scan_kernel() {
    __shared__ int wsum[32];
    int tid = threadIdx.x, lane = tid & 31, w = tid >> 5;
    int carry = 0;
    for (int base = 0; base < NN; base += 1024) {
        int idx = base + tid;
        int v = (idx < NN) ? g_deg[idx] : 0;
        int x = v;
        #pragma unroll
        for (int o = 1; o < 32; o <<= 1) {
            int t = __shfl_up_sync(0xffffffffu, x, o);
            if (lane >= o) x += t;
        }
        if (lane == 31) wsum[w] = x;
        __syncthreads();
        if (w == 0) {
            int s = wsum[lane];
            #pragma unroll
            for (int o = 1; o < 32; o <<= 1) {
                int t = __shfl_up_sync(0xffffffffu, s, o);
                if (lane >= o) s += t;
            }
            wsum[lane] = s;
        }
        __syncthreads();
        int excl = x - v + (w ? wsum[w - 1] : 0) + carry;
        if (idx < NN) { g_off[idx] = excl; g_cur[idx] = excl; }
        int total = wsum[31];
        __syncthreads();
        carry += total;
    }
    if (tid == 0) g_off[NN] = carry;
}

__global__ void scatter_kernel(const int* __restrict__ ei) {
    int e = blockIdx.x * blockDim.x + threadIdx.x;
    if (e < NE) {
        int d = ei[NE + e];
        int p = atomicAdd(&g_cur[d], 1);
        g_srcSorted[p] = ei[e];
    }
}

// ===================== weight convert: W[K,256] -> [N=256,K] bf16 hi/lo ========
__global__ void conv_w_kernel(const float* __restrict__ Wq, const float* __restrict__ Wk,
                              const float* __restrict__ Wv, const float* __restrict__ Ws,
                              const float* __restrict__ Wa, const float* __restrict__ Wb) {
    int mat = blockIdx.y;
    int K = (mat < 4) ? 1024 : 256;
    size_t off = (mat < 4) ? (size_t)mat * WBIG : (size_t)4 * WBIG + (size_t)(mat - 4) * WSML;
    const float* W = (mat == 0) ? Wq : (mat == 1) ? Wk : (mat == 2) ? Wv :
                     (mat == 3) ? Ws : (mat == 4) ? Wa : Wb;
    int idx = blockIdx.x * blockDim.x + threadIdx.x;
    if (idx < 256 * K) {
        int n = idx / K, k = idx % K;
        float w = W[(size_t)k * 256 + n];
        __nv_bfloat16 hi = __float2bfloat16(w);
        float r = w - __bfloat162float(hi);
        g_WH[off + idx] = hi;
        g_WL[off + idx] = __float2bfloat16(r);
    }
}

// ===================== HMMA GEMM (mma.sync bf16 3-product split) ===============
// Block: 128(M) x 256(N), BK=32, 256 threads = 8 warps of 64x64.
// SMEM stage: AH[128][40] AL[128][40] BH[256][40] BL[256][40] bf16 (pad 40 elems/row)
#define AH_OFF 0
#define AL_OFF 10240
#define BH_OFF 20480
#define BL_OFF 40960
#define STAGE  61440
#define GEMM_SMEM (2 * STAGE)

template <int KDIM>
__global__ __launch_bounds__(256, 1)
void mma_gemm(const float* __restrict__ X, int M, int matBase,
              const float* __restrict__ bias0, const float* __restrict__ bias1,
              const float* __restrict__ bias2, const float* __restrict__ bias3) {
    extern __shared__ char sm[];
    uint32_t smb = smem_u32(sm);
    int tid = threadIdx.x;
    int wid = tid >> 5;
    int lane = tid & 31;

    int mat = blockIdx.x;
    int m0 = blockIdx.y * 128;
    size_t wOff = (KDIM == 1024) ? (size_t)mat * WBIG
                                 : (size_t)4 * WBIG + (size_t)mat * WSML;
    const __nv_bfloat16* WH = g_WH + wOff;
    const __nv_bfloat16* WL = g_WL + wOff;
    const float* bias = (mat == 0) ? bias0 : (mat == 1) ? bias1 : (mat == 2) ? bias2 : bias3;
    float* O = out_sel(matBase + mat);

    // B cp.async source (global addresses)
    uint64_t gWH, gWL;
    {
        const __nv_bfloat16* ph = WH + (size_t)tid * KDIM;
        const __nv_bfloat16* pl = WL + (size_t)tid * KDIM;
        asm("cvta.to.global.u64 %0, %1;" : "=l"(gWH) : "l"(ph));
        asm("cvta.to.global.u64 %0, %1;" : "=l"(gWL) : "l"(pl));
    }
    uint32_t bDstH = smb + BH_OFF + (uint32_t)tid * 80u;
    uint32_t bDstL = smb + BL_OFF + (uint32_t)tid * 80u;

    // A loader mapping
    int ar = tid >> 1;
    int ah16 = (tid & 1) * 16;
    int arow = m0 + ar;
    bool avalid = (arow < M);
    const float* aSrc = X + (size_t)arow * KDIM + ah16;
    char* aDst = sm;  // stage offset added later

    // warp tiling
    int wm = (wid >> 2) * 64;
    int wn = (wid & 3) * 64;
    uint32_t a_row = (uint32_t)(wm + (lane & 7) + (lane & 8));
    uint32_t a_col = (uint32_t)((lane & 16) >> 1);          // 0 or 8
    uint32_t b_row = (uint32_t)(wn + ((lane & 16) >> 1) + (lane & 7));
    uint32_t b_col = (uint32_t)(lane & 8);                  // 0 or 8

    float c[4][8][4];
    #pragma unroll
    for (int i = 0; i < 4; i++)
        #pragma unroll
        for (int j = 0; j < 8; j++)
            #pragma unroll
            for (int u = 0; u < 4; u++) c[i][j][u] = 0.0f;

    constexpr int T = KDIM / 32;
    float4 areg[4];

    // ---- prologue: stage 0 ----
    {
        uint32_t db = 0;
        #pragma unroll
        for (int cc = 0; cc < 4; cc++) {
            CP16(bDstH + db + cc * 16, gWH + cc * 16);
            CP16(bDstL + db + cc * 16, gWL + cc * 16);
        }
        asm volatile("cp.async.commit_group;" ::: "memory");
        const float4 fz = make_float4(0.f, 0.f, 0.f, 0.f);
        #pragma unroll
        for (int cc = 0; cc < 4; cc++)
            areg[cc] = avalid ? ((const float4*)aSrc)[cc] : fz;
        // STS A stage 0
        #pragma unroll
        for (int cc = 0; cc < 4; cc++) {
            float vv[4] = {areg[cc].x, areg[cc].y, areg[cc].z, areg[cc].w};
            uint32_t h[4], l[4];
            #pragma unroll
            for (int u = 0; u < 4; u++) {
                __nv_bfloat16 bh = __float2bfloat16(vv[u]);
                float r = vv[u] - __bfloat162float(bh);
                h[u] = (uint32_t)__bfloat16_as_ushort(bh);
                l[u] = (uint32_t)__bfloat16_as_ushort(__float2bfloat16(r));
            }
            uint2 ph = make_uint2(h[0] | (h[1] << 16), h[2] | (h[3] << 16));
            uint2 pl = make_uint2(l[0] | (l[1] << 16), l[2] | (l[3] << 16));
            size_t off = (size_t)ar * 80 + (size_t)(ah16 + cc * 4) * 2;
            *(uint2*)(aDst + AH_OFF + off) = ph;
            *(uint2*)(aDst + AL_OFF + off) = pl;
        }
    }

    for (int t = 0; t < T; ++t) {
        int s = t & 1;
        asm volatile("cp.async.wait_group 0;" ::: "memory");
        __syncthreads();

        if (t + 1 < T) {
            uint32_t db = (uint32_t)(((t + 1) & 1) * STAGE);
            uint64_t koff = (uint64_t)(t + 1) * 64;  // 32 bf16 = 64 bytes
            #pragma unroll
            for (int cc = 0; cc < 4; cc++) {
                CP16(bDstH + db + cc * 16, gWH + koff + cc * 16);
                CP16(bDstL + db + cc * 16, gWL + koff + cc * 16);
            }
            asm volatile("cp.async.commit_group;" ::: "memory");
            const float4 fz = make_float4(0.f, 0.f, 0.f, 0.f);
            const float* ap = aSrc + (t + 1) * 32;
            #pragma unroll
            for (int cc = 0; cc < 4; cc++)
                areg[cc] = avalid ? ((const float4*)ap)[cc] : fz;
        }

        // ---- compute chunk t from stage s ----
        uint32_t sb = smb + (uint32_t)(s * STAGE);
        #pragma unroll
        for (int ks = 0; ks < 2; ks++) {
            uint32_t ahr[4][4], alr[4][4];
            #pragma unroll
            for (int i = 0; i < 4; i++) {
                uint32_t off = (a_row + i * 16) * 80u + (ks * 16 + a_col) * 2u;
                LDM_X4(ahr[i][0], ahr[i][1], ahr[i][2], ahr[i][3], sb + AH_OFF + off);
                LDM_X4(alr[i][0], alr[i][1], alr[i][2], alr[i][3], sb + AL_OFF + off);
            }
            uint32_t bhr[8][2];
            #pragma unroll
            for (int p = 0; p < 4; p++) {
                uint32_t off = (b_row + p * 16) * 80u + (ks * 16 + b_col) * 2u;
                LDM_X4(bhr[2 * p][0], bhr[2 * p][1], bhr[2 * p + 1][0], bhr[2 * p + 1][1],
                       sb + BH_OFF + off);
            }
            #pragma unroll
            for (int i = 0; i < 4; i++)
                #pragma unroll
                for (int j = 0; j < 8; j++) mma_bf16(c[i][j], ahr[i], bhr[j]);
            #pragma unroll
            for (int i = 0; i < 4; i++)
                #pragma unroll
                for (int j = 0; j < 8; j++) mma_bf16(c[i][j], alr[i], bhr[j]);
            uint32_t blr[8][2];
            #pragma unroll
            for (int p = 0; p < 4; p++) {
                uint32_t off = (b_row + p * 16) * 80u + (ks * 16 + b_col) * 2u;
                LDM_X4(blr[2 * p][0], blr[2 * p][1], blr[2 * p + 1][0], blr[2 * p + 1][1],
                       sb + BL_OFF + off);
            }
            #pragma unroll
            for (int i = 0; i < 4; i++)
                #pragma unroll
                for (int j = 0; j < 8; j++) mma_bf16(c[i][j], ahr[i], blr[j]);
        }

        if (t + 1 < T) {
            char* dst = sm + ((t + 1) & 1) * STAGE;
            #pragma unroll
            for (int cc = 0; cc < 4; cc++) {
                float vv[4] = {areg[cc].x, areg[cc].y, areg[cc].z, areg[cc].w};
                uint32_t h[4], l[4];
                #pragma unroll
                for (int u = 0; u < 4; u++) {
                    __nv_bfloat16 bh = __float2bfloat16(vv[u]);
                    float r = vv[u] - __bfloat162float(bh);
                    h[u] = (uint32_t)__bfloat16_as_ushort(bh);
                    l[u] = (uint32_t)__bfloat16_as_ushort(__float2bfloat16(r));
                }
                uint2 ph = make_uint2(h[0] | (h[1] << 16), h[2] | (h[3] << 16));
                uint2 pl = make_uint2(l[0] | (l[1] << 16), l[2] | (l[3] << 16));
                size_t off = (size_t)ar * 80 + (size_t)(ah16 + cc * 4) * 2;
                *(uint2*)(dst + AH_OFF + off) = ph;
                *(uint2*)(dst + AL_OFF + off) = pl;
            }
        }
    }

    // ---- epilogue: bias + store ----
    #pragma unroll
    for (int i = 0; i < 4; i++) {
        int r0 = m0 + wm + i * 16 + (lane >> 2);
        int r1 = r0 + 8;
        #pragma unroll
        for (int j = 0; j < 8; j++) {
            int cc = wn + j * 8 + (lane & 3) * 2;
            float bx = bias[cc], by = bias[cc + 1];
            if (r0 < M) {
                float2 v = make_float2(c[i][j][0] + bx, c[i][j][1] + by);
                *(float2*)(O + (size_t)r0 * 256 + cc) = v;
            }
            if (r1 < M) {
                float2 v = make_float2(c[i][j][2] + bx, c[i][j][3] + by);
                *(float2*)(O + (size_t)r1 * 256 + cc) = v;
            }
        }
    }
}

// ===================== fused edge softmax + aggregation + residual + gelu ======
__global__ __launch_bounds__(256)
void attn_kernel(float* __restrict__ hOut) {
    int warp = (blockIdx.x * blockDim.x + threadIdx.x) >> 5;
    int lane = threadIdx.x & 31;
    if (warp >= NN) return;
    int d = warp;

    const float4* Qr = (const float4*)(g_Q + (size_t)d * 256);
    float4 q0 = Qr[lane], q1 = Qr[lane + 32];
    int e0 = g_off[d], e1 = g_off[d + 1];

    float amax = -INFINITY;
    for (int e = e0; e < e1; ++e) {
        int s = g_srcSorted[e];
        const float4* Kr = (const float4*)(g_K + (size_t)s * 256);
        float4 k0 = Kr[lane], k1 = Kr[lane + 32];
        float dot = q0.x * k0.x + q0.y * k0.y + q0.z * k0.z + q0.w * k0.w
                  + q1.x * k1.x + q1.y * k1.y + q1.z * k1.z + q1.w * k1.w;
        #pragma unroll
        for (int o = 16; o; o >>= 1) dot += __shfl_xor_sync(0xffffffffu, dot, o);
        dot *= 0.0625f;
        g_alpha[e] = dot;
        amax = fmaxf(amax, dot);
    }

    float den = 0.0f;
    float4 acc0 = make_float4(0, 0, 0, 0), acc1 = make_float4(0, 0, 0, 0);
    for (int e = e0; e < e1; ++e) {
        float w = expf(g_alpha[e] - amax);
        den += w;
        int s = g_srcSorted[e];
        const float4* Vr = (const float4*)(g_V + (size_t)s * 256);
        float4 v0 = Vr[lane], v1 = Vr[lane + 32];
        acc0.x += w * v0.x; acc0.y += w * v0.y; acc0.z += w * v0.z; acc0.w += w * v0.w;
        acc1.x += w * v1.x; acc1.y += w * v1.y; acc1.z += w * v1.z; acc1.w += w * v1.w;
    }
    float inv = 1.0f / (den + 1e-16f);

    const float4* Sr = (const float4*)(g_S + (size_t)d * 256);
    float4 s0 = Sr[lane], s1 = Sr[lane + 32];
    float4 h0, h1;
    h0.x = gelu_exact(acc0.x * inv + s0.x);
    h0.y = gelu_exact(acc0.y * inv + s0.y);
    h0.z = gelu_exact(acc0.z * inv + s0.z);
    h0.w = gelu_exact(acc0.w * inv + s0.w);
    h1.x = gelu_exact(acc1.x * inv + s1.x);
    h1.y = gelu_exact(acc1.y * inv + s1.y);
    h1.z = gelu_exact(acc1.z * inv + s1.z);
    h1.w = gelu_exact(acc1.w * inv + s1.w);

    float4* Hr = (float4*)(hOut + (size_t)d * 256);
    Hr[lane] = h0;
    Hr[lane + 32] = h1;
}

// ===================== gate + scores =====================
__global__ __launch_bounds__(256)
void act_scores_kernel(const float* __restrict__ Wc, const float* __restrict__ bc) {
    int warp = (blockIdx.x * blockDim.x + threadIdx.x) >> 5;
    int lane = threadIdx.x & 31;
    if (warp >= NN) return;
    int n = warp;

    const float4* Ar = (const float4*)(g_TA + (size_t)n * 256);
    const float4* Br = (const float4*)(g_TB + (size_t)n * 256);
    float s0 = 0.0f, s1 = 0.0f;
    #pragma unroll
    for (int part = 0; part < 2; part++) {
        int idx = lane + part * 32;
        float4 av = Ar[idx], bv = Br[idx];
        float aa[4] = {av.x, av.y, av.z, av.w};
        float bb[4] = {bv.x, bv.y, bv.z, bv.w};
        int jbase = idx * 4;
        #pragma unroll
        for (int u = 0; u < 4; u++) {
            float a = tanhf(aa[u]);
            float b = 1.0f / (1.0f + expf(-bb[u]));
            float g = a * b;
            s0 += g * Wc[(jbase + u) * 2 + 0];
            s1 += g * Wc[(jbase + u) * 2 + 1];
        }
    }
    #pragma unroll
    for (int o = 16; o; o >>= 1) {
        s0 += __shfl_xor_sync(0xffffffffu, s0, o);
        s1 += __shfl_xor_sync(0xffffffffu, s1, o);
    }
    if (lane == 0) {
        g_scores[2 * n + 0] = s0 + bc[0];
        g_scores[2 * n + 1] = s1 + bc[1];
    }
}

// ===================== column softmax stats =====================
__global__ void softmax_stats_kernel() {
    __shared__ float sh[1024];
    int tid = threadIdx.x;
    float m0 = -INFINITY, m1 = -INFINITY;
    for (int i = tid; i < NN; i += 1024) {
        m0 = fmaxf(m0, g_scores[2 * i]);
        m1 = fmaxf(m1, g_scores[2 * i + 1]);
    }
    sh[tid] = m0; __syncthreads();
    for (int o = 512; o; o >>= 1) { if (tid < o) sh[tid] = fmaxf(sh[tid], sh[tid + o]); __syncthreads(); }
    float cm0 = sh[0]; __syncthreads();
    sh[tid] = m1; __syncthreads();
    for (int o = 512; o; o >>= 1) { if (tid < o) sh[tid] = fmaxf(sh[tid], sh[tid + o]); __syncthreads(); }
    float cm1 = sh[0]; __syncthreads();

    float s0 = 0.0f, s1 = 0.0f;
    for (int i = tid; i < NN; i += 1024) {
        s0 += expf(g_scores[2 * i] - cm0);
        s1 += expf(g_scores[2 * i + 1] - cm1);
    }
    sh[tid] = s0; __syncthreads();
    for (int o = 512; o; o >>= 1) { if (tid < o) sh[tid] += sh[tid + o]; __syncthreads(); }
    float sum0 = sh[0]; __syncthreads();
    sh[tid] = s1; __syncthreads();
    for (int o = 512; o; o >>= 1) { if (tid < o) sh[tid] += sh[tid + o]; __syncthreads(); }
    float sum1 = sh[0];
    if (tid == 0) {
        g_cmax[0] = cm0; g_cmax[1] = cm1;
        g_csum[0] = sum0; g_csum[1] = sum1;
    }
}

// ===================== attn output, A, y = attn.T @ h =====================
__global__ __launch_bounds__(256)
void output_kernel(const int* __restrict__ label,
                   const float* __restrict__ h,
                   float* __restrict__ out) {
    int t = threadIdx.x;
    float cm0 = g_cmax[0], cm1 = g_cmax[1];
    float is0 = 1.0f / g_csum[0], is1 = 1.0f / g_csum[1];
    int lbl = *label;
    float y0 = 0.0f, y1 = 0.0f;
    for (int n = blockIdx.x; n < NN; n += gridDim.x) {
        float sc0 = g_scores[2 * n], sc1 = g_scores[2 * n + 1];
        float a0 = expf(sc0 - cm0) * is0;
        float a1 = expf(sc1 - cm1) * is1;
        if (t == 0) out[512 + n] = (lbl == 0) ? a0 : a1;
        float hv = h[(size_t)n * 256 + t];
        y0 += a0 * hv;
        y1 += a1 * hv;
    }
    atomicAdd(&out[t], y0);
    atomicAdd(&out[256 + t], y1);
}

// ===================== launch =====================
extern "C" void kernel_launch(void* const* d_in, const int* in_sizes, int n_in,
                              void* d_out, int out_size) {
    const float* x  = (const float*)d_in[0];
    const float* Wq = (const float*)d_in[1];  const float* bq = (const float*)d_in[2];
    const float* Wk = (const float*)d_in[3];  const float* bk = (const float*)d_in[4];
    const float* Wv = (const float*)d_in[5];  const float* bv = (const float*)d_in[6];
    const float* Ws = (const float*)d_in[7];  const float* bs = (const float*)d_in[8];
    const float* Wa = (const float*)d_in[9];  const float* ba = (const float*)d_in[10];
    const float* Wb = (const float*)d_in[11]; const float* bb = (const float*)d_in[12];
    const float* Wc = (const float*)d_in[13]; const float* bc = (const float*)d_in[14];
    const int*   ei = (const int*)d_in[15];
    const int*   lb = (const int*)d_in[16];

    float* out  = (float*)d_out;
    float* hOut = out + 512 + NN;

    cudaFuncSetAttribute(mma_gemm<LIN>, cudaFuncAttributeMaxDynamicSharedMemorySize, GEMM_SMEM);
    cudaFuncSetAttribute(mma_gemm<DH>,  cudaFuncAttributeMaxDynamicSharedMemorySize, GEMM_SMEM);

    init_kernel<<<(NN + 255) / 256, 256>>>(out);
    count_kernel<<<(NE + 255) / 256, 256>>>(ei);
    scan_kernel<<<1, 1024>>>();
    scatter_kernel<<<(NE + 255) / 256, 256>>>(ei);

    conv_w_kernel<<<dim3((256 * 1024 + 255) / 256, 6), 256>>>(Wq, Wk, Wv, Ws, Wa, Wb);

    // Q|K|V|S = x @ [Wq Wk Wv Ws] + biases  (HMMA bf16-split)
    mma_gemm<LIN><<<dim3(4, (NN + 127) / 128), 256, GEMM_SMEM>>>(
        x, NN, 0, bq, bk, bv, bs);

    attn_kernel<<<(NN * 32 + 255) / 256, 256>>>(hOut);

    // TA|TB = h @ [Wa Wb] + biases
    mma_gemm<DH><<<dim3(2, (NN + 127) / 128), 256, GEMM_SMEM>>>(
        hOut, NN, 4, ba, bb, ba, ba);

    act_scores_kernel<<<(NN * 32 + 255) / 256, 256>>>(Wc, bc);
    softmax_stats_kernel<<<1, 1024>>>();
    output_kernel<<<512, 256>>>(lb, hOut, out);
}

// round 5
// speedup vs baseline: 2.3574x; 1.3833x over previous
#include <cuda_runtime.h>
#include <cuda_fp16.h>
#include <math.h>
#include <stdint.h>

#define NN 50000
#define NE 800000
#define LIN 1024
#define DH 256

// ===================== scratch (static device globals) =====================
__device__ float g_Q[(size_t)NN * DH];
__device__ __half g_Kh[(size_t)NN * DH];
__device__ float g_V[(size_t)NN * DH];
__device__ float g_S[(size_t)NN * DH];
__device__ float g_TA[(size_t)NN * DH];
__device__ float g_TB[(size_t)NN * DH];
__device__ float g_alpha[NE];
__device__ int   g_srcSorted[NE];
__device__ int   g_deg[NN];
__device__ int   g_off[NN + 1];
__device__ int   g_cur[NN];
__device__ float g_scores[NN * 2];
__device__ float g_cmax[2];
__device__ float g_csum[2];

// fp16 split weights, transposed to [N=256, K] per matrix (k-major rows).
#define WBIG (256 * 1024)
#define WSML (256 * 256)
__device__ __half g_WH[4 * WBIG + 2 * WSML];
__device__ __half g_WL[4 * WBIG + 2 * WSML];

__device__ __forceinline__ float* out_sel(int s) {
    switch (s) {
        case 0: return g_Q;
        case 2: return g_V;
        case 3: return g_S;
        case 4: return g_TA;
        default: return g_TB;
    }
}

__device__ __forceinline__ float gelu_exact(float x) {
    return 0.5f * x * (1.0f + erff(x * 0.70710678118654752440f));
}

__device__ __forceinline__ uint32_t smem_u32(const void* p) {
    uint32_t a;
    asm("{ .reg .u64 t; cvta.to.shared.u64 t, %1; cvt.u32.u64 %0, t; }" : "=r"(a) : "l"(p));
    return a;
}

#define LDM_X4(r0, r1, r2, r3, addr) \
    asm volatile("ldmatrix.sync.aligned.m8n8.x4.shared.b16 {%0,%1,%2,%3}, [%4];" \
                 : "=r"(r0), "=r"(r1), "=r"(r2), "=r"(r3) : "r"(addr))

#define CP16(dst, src) \
    asm volatile("cp.async.cg.shared.global [%0], [%1], 16;" :: "r"(dst), "l"(src))

__device__ __forceinline__ void mma_f16(float* d, const uint32_t* a, const uint32_t* b) {
    asm volatile(
        "mma.sync.aligned.m16n8k16.row.col.f32.f16.f16.f32 "
        "{%0,%1,%2,%3},{%4,%5,%6,%7},{%8,%9},{%0,%1,%2,%3};"
        : "+f"(d[0]), "+f"(d[1]), "+f"(d[2]), "+f"(d[3])
        : "r"(a[0]), "r"(a[1]), "r"(a[2]), "r"(a[3]), "r"(b[0]), "r"(b[1]));
}

// ===================== init =====================
__global__ void init_kernel(float* __restrict__ out) {
    int i = blockIdx.x * blockDim.x + threadIdx.x;
    if (i < NN) g_deg[i] = 0;
    if (i < 512) out[i] = 0.0f;
}

// ===================== CSR build =====================
__global__ void count_kernel(const int* __restrict__ ei) {
    int e = blockIdx.x * blockDim.x + threadIdx.x;
    if (e < NE) atomicAdd(&g_deg[ei[NE + e]], 1);
}

__global__ void scan_kernel() {
    __shared__ int wsum[32];
    int tid = threadIdx.x, lane = tid & 31, w = tid >> 5;
    int carry = 0;
    for (int base = 0; base < NN; base += 1024) {
        int idx = base + tid;
        int v = (idx < NN) ? g_deg[idx] : 0;
        int x = v;
        #pragma unroll
        for (int o = 1; o < 32; o <<= 1) {
            int t = __shfl_up_sync(0xffffffffu, x, o);
            if (lane >= o) x += t;
        }
        if (lane == 31) wsum[w] = x;
        __syncthreads();
        if (w == 0) {
            int s = wsum[lane];
            #pragma unroll
            for (int o = 1; o < 32; o <<= 1) {
                int t = __shfl_up_sync(0xffffffffu, s, o);
                if (lane >= o) s += t;
            }
            wsum[lane] = s;
        }
        __syncthreads();
        int excl = x - v + (w ? wsum[w - 1] : 0) + carry;
        if (idx < NN) { g_off[idx] = excl; g_cur[idx] = excl; }
        int total = wsum[31];
        __syncthreads();
        carry += total;
    }
    if (tid == 0) g_off[NN] = carry;
}

__global__ void scatter_kernel(const int* __restrict__ ei) {
    int e = blockIdx.x * blockDim.x + threadIdx.x;
    if (e < NE) {
        int d = ei[NE + e];
        int p = atomicAdd(&g_cur[d], 1);
        g_srcSorted[p] = ei[e];
    }
}

// ===================== weight convert: W[K,256] -> [N=256,K] fp16 hi/lo ========
__global__ void conv_w_kernel(const float* __restrict__ Wq, const float* __restrict__ Wk,
                              const float* __restrict__ Wv, const float* __restrict__ Ws,
                              const float* __restrict__ Wa, const float* __restrict__ Wb) {
    int mat = blockIdx.y;
    int K = (mat < 4) ? 1024 : 256;
    size_t off = (mat < 4) ? (size_t)mat * WBIG : (size_t)4 * WBIG + (size_t)(mat - 4) * WSML;
    const float* W = (mat == 0) ? Wq : (mat == 1) ? Wk : (mat == 2) ? Wv :
                     (mat == 3) ? Ws : (mat == 4) ? Wa : Wb;
    int idx = blockIdx.x * blockDim.x + threadIdx.x;
    if (idx < 256 * K) {
        int n = idx / K, k = idx % K;
        float w = W[(size_t)k * 256 + n];
        __half hi = __float2half_rn(w);
        float r = w - __half2float(hi);
        g_WH[off + idx] = hi;
        g_WL[off + idx] = __float2half_rn(r);
    }
}

// ===================== HMMA GEMM (fp16 2-product weight-split) =================
// Block: 96(M) x 256(N), BK=32, 384 threads = 12 warps of 32x64.
// SMEM stage: AH[96][40] fp16, BH[256][40], BL[256][40] fp16 (pad 40 elems/row)
#define AH_OFF 0
#define BH_OFF 7680
#define BL_OFF 28160
#define STAGE  48640
#define GEMM_SMEM (2 * STAGE)
#define BM 96

template <int KDIM>
__global__ __launch_bounds__(384, 1)
void mma_gemm(const float* __restrict__ X, int M, int matBase,
              const float* __restrict__ bias0, const float* __restrict__ bias1,
              const float* __restrict__ bias2, const float* __restrict__ bias3) {
    extern __shared__ char sm[];
    uint32_t smb = smem_u32(sm);
    int tid = threadIdx.x;
    int wid = tid >> 5;
    int lane = tid & 31;

    int mat = blockIdx.x;
    int m0 = blockIdx.y * BM;
    size_t wOff = (KDIM == 1024) ? (size_t)mat * WBIG
                                 : (size_t)4 * WBIG + (size_t)mat * WSML;
    const float* bias = (mat == 0) ? bias0 : (mat == 1) ? bias1 : (mat == 2) ? bias2 : bias3;
    bool toHalf = (matBase == 0 && mat == 1);
    float* Of = out_sel(matBase + mat);

    uint64_t gWH, gWL;
    {
        const __half* ph = g_WH + wOff;
        const __half* pl = g_WL + wOff;
        asm("cvta.to.global.u64 %0, %1;" : "=l"(gWH) : "l"(ph));
        asm("cvta.to.global.u64 %0, %1;" : "=l"(gWL) : "l"(pl));
    }

    // A loader mapping: 96 rows x 32 cols fp32; tid -> row=tid>>2, q=tid&3 (8 cols)
    int ar = tid >> 2;
    int aq = tid & 3;
    int arow = m0 + ar;
    bool avalid = (arow < M);
    const float* aSrc = X + (size_t)arow * KDIM + aq * 8;

    // warp tiling: wm in {0,32,64}, wn in {0,64,128,192}
    int wm = (wid >> 2) * 32;
    int wn = (wid & 3) * 64;
    uint32_t a_row = (uint32_t)(wm + (lane & 7) + (lane & 8));
    uint32_t a_col = (uint32_t)((lane & 16) >> 1);
    uint32_t b_row = (uint32_t)(wn + ((lane & 16) >> 1) + (lane & 7));
    uint32_t b_col = (uint32_t)(lane & 8);

    float c[2][8][4];
    #pragma unroll
    for (int i = 0; i < 2; i++)
        #pragma unroll
        for (int j = 0; j < 8; j++)
            #pragma unroll
            for (int u = 0; u < 4; u++) c[i][j][u] = 0.0f;

    constexpr int T = KDIM / 32;
    float4 areg[2];

    // ---- B cp.async issue for chunk t into stage st ----
    auto issueB = [&](int t, int st) {
        uint32_t db = smb + (uint32_t)(st * STAGE);
        uint64_t koff = (uint64_t)t * 64;  // 32 halfs = 64 bytes
        for (int i = tid; i < 1024; i += 384) {
            int row = i >> 2, quad = i & 3;
            uint32_t d = db + BH_OFF + (uint32_t)row * 80u + (uint32_t)quad * 16u;
            CP16(d, gWH + (uint64_t)row * (KDIM * 2) + koff + quad * 16);
        }
        for (int i = tid; i < 1024; i += 384) {
            int row = i >> 2, quad = i & 3;
            uint32_t d = db + BL_OFF + (uint32_t)row * 80u + (uint32_t)quad * 16u;
            CP16(d, gWL + (uint64_t)row * (KDIM * 2) + koff + quad * 16);
        }
        asm volatile("cp.async.commit_group;" ::: "memory");
    };

    auto ldA = [&](int t) {
        const float4 fz = make_float4(0.f, 0.f, 0.f, 0.f);
        const float* p = aSrc + t * 32;
        areg[0] = avalid ? ((const float4*)p)[0] : fz;
        areg[1] = avalid ? ((const float4*)p)[1] : fz;
    };

    auto stsA = [&](int st) {
        uint32_t h[8];
        float vv[8] = {areg[0].x, areg[0].y, areg[0].z, areg[0].w,
                       areg[1].x, areg[1].y, areg[1].z, areg[1].w};
        #pragma unroll
        for (int u = 0; u < 8; u++)
            h[u] = (uint32_t)__half_as_ushort(__float2half_rn(vv[u]));
        uint4 pk;
        pk.x = h[0] | (h[1] << 16); pk.y = h[2] | (h[3] << 16);
        pk.z = h[4] | (h[5] << 16); pk.w = h[6] | (h[7] << 16);
        *(uint4*)(sm + st * STAGE + AH_OFF + (size_t)ar * 80 + (size_t)aq * 16) = pk;
    };

    // ---- prologue ----
    issueB(0, 0);
    ldA(0);
    stsA(0);

    for (int t = 0; t < T; ++t) {
        int s = t & 1;
        asm volatile("cp.async.wait_group 0;" ::: "memory");
        __syncthreads();

        if (t + 1 < T) {
            issueB(t + 1, (t + 1) & 1);
            ldA(t + 1);
        }

        uint32_t sb = smb + (uint32_t)(s * STAGE);
        #pragma unroll
        for (int ks = 0; ks < 2; ks++) {
            uint32_t ahr[2][4];
            #pragma unroll
            for (int i = 0; i < 2; i++) {
                uint32_t off = (a_row + i * 16) * 80u + (ks * 16 + a_col) * 2u;
                LDM_X4(ahr[i][0], ahr[i][1], ahr[i][2], ahr[i][3], sb + AH_OFF + off);
            }
            uint32_t bhr[8][2];
            #pragma unroll
            for (int p = 0; p < 4; p++) {
                uint32_t off = (b_row + p * 16) * 80u + (ks * 16 + b_col) * 2u;
                LDM_X4(bhr[2 * p][0], bhr[2 * p][1], bhr[2 * p + 1][0], bhr[2 * p + 1][1],
                       sb + BH_OFF + off);
            }
            #pragma unroll
            for (int i = 0; i < 2; i++)
                #pragma unroll
                for (int j = 0; j < 8; j++) mma_f16(c[i][j], ahr[i], bhr[j]);
            uint32_t blr[8][2];
            #pragma unroll
            for (int p = 0; p < 4; p++) {
                uint32_t off = (b_row + p * 16) * 80u + (ks * 16 + b_col) * 2u;
                LDM_X4(blr[2 * p][0], blr[2 * p][1], blr[2 * p + 1][0], blr[2 * p + 1][1],
                       sb + BL_OFF + off);
            }
            #pragma unroll
            for (int i = 0; i < 2; i++)
                #pragma unroll
                for (int j = 0; j < 8; j++) mma_f16(c[i][j], ahr[i], blr[j]);
        }

        if (t + 1 < T) stsA((t + 1) & 1);
    }

    // ---- epilogue: bias + store ----
    #pragma unroll
    for (int i = 0; i < 2; i++) {
        int r0 = m0 + wm + i * 16 + (lane >> 2);
        int r1 = r0 + 8;
        #pragma unroll
        for (int j = 0; j < 8; j++) {
            int cc = wn + j * 8 + (lane & 3) * 2;
            float bx = bias[cc], by = bias[cc + 1];
            if (toHalf) {
                if (r0 < M)
                    *(__half2*)(g_Kh + (size_t)r0 * 256 + cc) =
                        __floats2half2_rn(c[i][j][0] + bx, c[i][j][1] + by);
                if (r1 < M)
                    *(__half2*)(g_Kh + (size_t)r1 * 256 + cc) =
                        __floats2half2_rn(c[i][j][2] + bx, c[i][j][3] + by);
            } else {
                if (r0 < M) {
                    float2 v = make_float2(c[i][j][0] + bx, c[i][j][1] + by);
                    *(float2*)(Of + (size_t)r0 * 256 + cc) = v;
                }
                if (r1 < M) {
                    float2 v = make_float2(c[i][j][2] + bx, c[i][j][3] + by);
                    *(float2*)(Of + (size_t)r1 * 256 + cc) = v;
                }
            }
        }
    }
}

// ===================== fused edge softmax + aggregation + residual + gelu ======
__global__ __launch_bounds__(256)
void attn_kernel(float* __restrict__ hOut) {
    int warp = (blockIdx.x * blockDim.x + threadIdx.x) >> 5;
    int lane = threadIdx.x & 31;
    if (warp >= NN) return;
    int d = warp;

    const float4* Qr = (const float4*)(g_Q + (size_t)d * 256);
    float4 q0 = Qr[2 * lane], q1 = Qr[2 * lane + 1];
    int e0 = g_off[d], e1 = g_off[d + 1];

    float amax = -INFINITY;
    for (int e = e0; e < e1; ++e) {
        int s = g_srcSorted[e];
        uint4 kk = *(const uint4*)(g_Kh + (size_t)s * 256 + lane * 8);
        float2 k0 = __half22float2(*(__half2*)&kk.x);
        float2 k1 = __half22float2(*(__half2*)&kk.y);
        float2 k2 = __half22float2(*(__half2*)&kk.z);
        float2 k3 = __half22float2(*(__half2*)&kk.w);
        float dot = q0.x * k0.x + q0.y * k0.y + q0.z * k1.x + q0.w * k1.y
                  + q1.x * k2.x + q1.y * k2.y + q1.z * k3.x + q1.w * k3.y;
        #pragma unroll
        for (int o = 16; o; o >>= 1) dot += __shfl_xor_sync(0xffffffffu, dot, o);
        dot *= 0.0625f;
        g_alpha[e] = dot;
        amax = fmaxf(amax, dot);
    }

    float den = 0.0f;
    float4 acc0 = make_float4(0, 0, 0, 0), acc1 = make_float4(0, 0, 0, 0);
    for (int e = e0; e < e1; ++e) {
        float w = expf(g_alpha[e] - amax);
        den += w;
        int s = g_srcSorted[e];
        const float4* Vr = (const float4*)(g_V + (size_t)s * 256);
        float4 v0 = Vr[2 * lane], v1 = Vr[2 * lane + 1];
        acc0.x += w * v0.x; acc0.y += w * v0.y; acc0.z += w * v0.z; acc0.w += w * v0.w;
        acc1.x += w * v1.x; acc1.y += w * v1.y; acc1.z += w * v1.z; acc1.w += w * v1.w;
    }
    float inv = 1.0f / (den + 1e-16f);

    const float4* Sr = (const float4*)(g_S + (size_t)d * 256);
    float4 s0 = Sr[2 * lane], s1 = Sr[2 * lane + 1];
    float4 h0, h1;
    h0.x = gelu_exact(acc0.x * inv + s0.x);
    h0.y = gelu_exact(acc0.y * inv + s0.y);
    h0.z = gelu_exact(acc0.z * inv + s0.z);
    h0.w = gelu_exact(acc0.w * inv + s0.w);
    h1.x = gelu_exact(acc1.x * inv + s1.x);
    h1.y = gelu_exact(acc1.y * inv + s1.y);
    h1.z = gelu_exact(acc1.z * inv + s1.z);
    h1.w = gelu_exact(acc1.w * inv + s1.w);

    float4* Hr = (float4*)(hOut + (size_t)d * 256);
    Hr[2 * lane] = h0;
    Hr[2 * lane + 1] = h1;
}

// ===================== gate + scores =====================
__global__ __launch_bounds__(256)
void act_scores_kernel(const float* __restrict__ Wc, const float* __restrict__ bc) {
    int warp = (blockIdx.x * blockDim.x + threadIdx.x) >> 5;
    int lane = threadIdx.x & 31;
    if (warp >= NN) return;
    int n = warp;

    const float4* Ar = (const float4*)(g_TA + (size_t)n * 256);
    const float4* Br = (const float4*)(g_TB + (size_t)n * 256);
    float s0 = 0.0f, s1 = 0.0f;
    #pragma unroll
    for (int part = 0; part < 2; part++) {
        int idx = 2 * lane + part;
        float4 av = Ar[idx], bv = Br[idx];
        float aa[4] = {av.x, av.y, av.z, av.w};
        float bb[4] = {bv.x, bv.y, bv.z, bv.w};
        int jbase = idx * 4;
        #pragma unroll
        for (int u = 0; u < 4; u++) {
            float a = tanhf(aa[u]);
            float b = 1.0f / (1.0f + expf(-bb[u]));
            float g = a * b;
            s0 += g * Wc[(jbase + u) * 2 + 0];
            s1 += g * Wc[(jbase + u) * 2 + 1];
        }
    }
    #pragma unroll
    for (int o = 16; o; o >>= 1) {
        s0 += __shfl_xor_sync(0xffffffffu, s0, o);
        s1 += __shfl_xor_sync(0xffffffffu, s1, o);
    }
    if (lane == 0) {
        g_scores[2 * n + 0] = s0 + bc[0];
        g_scores[2 * n + 1] = s1 + bc[1];
    }
}

// ===================== column softmax stats =====================
__global__ void softmax_stats_kernel() {
    __shared__ float sh[1024];
    int tid = threadIdx.x;
    float m0 = -INFINITY, m1 = -INFINITY;
    for (int i = tid; i < NN; i += 1024) {
        m0 = fmaxf(m0, g_scores[2 * i]);
        m1 = fmaxf(m1, g_scores[2 * i + 1]);
    }
    sh[tid] = m0; __syncthreads();
    for (int o = 512; o; o >>= 1) { if (tid < o) sh[tid] = fmaxf(sh[tid], sh[tid + o]); __syncthreads(); }
    float cm0 = sh[0]; __syncthreads();
    sh[tid] = m1; __syncthreads();
    for (int o = 512; o; o >>= 1) { if (tid < o) sh[tid] = fmaxf(sh[tid], sh[tid + o]); __syncthreads(); }
    float cm1 = sh[0]; __syncthreads();

    float s0 = 0.0f, s1 = 0.0f;
    for (int i = tid; i < NN; i += 1024) {
        s0 += expf(g_scores[2 * i] - cm0);
        s1 += expf(g_scores[2 * i + 1] - cm1);
    }
    sh[tid] = s0; __syncthreads();
    for (int o = 512; o; o >>= 1) { if (tid < o) sh[tid] += sh[tid + o]; __syncthreads(); }
    float sum0 = sh[0]; __syncthreads();
    sh[tid] = s1; __syncthreads();
    for (int o = 512; o; o >>= 1) { if (tid < o) sh[tid] += sh[tid + o]; __syncthreads(); }
    float sum1 = sh[0];
    if (tid == 0) {
        g_cmax[0] = cm0; g_cmax[1] = cm1;
        g_csum[0] = sum0; g_csum[1] = sum1;
    }
}

// ===================== attn output, A, y = attn.T @ h =====================
__global__ __launch_bounds__(256)
void output_kernel(const int* __restrict__ label,
                   const float* __restrict__ h,
                   float* __restrict__ out) {
    int t = threadIdx.x;
    float cm0 = g_cmax[0], cm1 = g_cmax[1];
    float is0 = 1.0f / g_csum[0], is1 = 1.0f / g_csum[1];
    int lbl = *label;
    float y0 = 0.0f, y1 = 0.0f;
    for (int n = blockIdx.x; n < NN; n += gridDim.x) {
        float sc0 = g_scores[2 * n], sc1 = g_scores[2 * n + 1];
        float a0 = expf(sc0 - cm0) * is0;
        float a1 = expf(sc1 - cm1) * is1;
        if (t == 0) out[512 + n] = (lbl == 0) ? a0 : a1;
        float hv = h[(size_t)n * 256 + t];
        y0 += a0 * hv;
        y1 += a1 * hv;
    }
    atomicAdd(&out[t], y0);
    atomicAdd(&out[256 + t], y1);
}

// ===================== launch =====================
extern "C" void kernel_launch(void* const* d_in, const int* in_sizes, int n_in,
                              void* d_out, int out_size) {
    const float* x  = (const float*)d_in[0];
    const float* Wq = (const float*)d_in[1];  const float* bq = (const float*)d_in[2];
    const float* Wk = (const float*)d_in[3];  const float* bk = (const float*)d_in[4];
    const float* Wv = (const float*)d_in[5];  const float* bv = (const float*)d_in[6];
    const float* Ws = (const float*)d_in[7];  const float* bs = (const float*)d_in[8];
    const float* Wa = (const float*)d_in[9];  const float* ba = (const float*)d_in[10];
    const float* Wb = (const float*)d_in[11]; const float* bb = (const float*)d_in[12];
    const float* Wc = (const float*)d_in[13]; const float* bc = (const float*)d_in[14];
    const int*   ei = (const int*)d_in[15];
    const int*   lb = (const int*)d_in[16];

    float* out  = (float*)d_out;
    float* hOut = out + 512 + NN;

    cudaFuncSetAttribute(mma_gemm<LIN>, cudaFuncAttributeMaxDynamicSharedMemorySize, GEMM_SMEM);
    cudaFuncSetAttribute(mma_gemm<DH>,  cudaFuncAttributeMaxDynamicSharedMemorySize, GEMM_SMEM);

    init_kernel<<<(NN + 255) / 256, 256>>>(out);
    count_kernel<<<(NE + 255) / 256, 256>>>(ei);
    scan_kernel<<<1, 1024>>>();
    scatter_kernel<<<(NE + 255) / 256, 256>>>(ei);

    conv_w_kernel<<<dim3((256 * 1024 + 255) / 256, 6), 256>>>(Wq, Wk, Wv, Ws, Wa, Wb);

    // Q|K|V|S = x @ [Wq Wk Wv Ws] + biases  (HMMA fp16 2-product)
    mma_gemm<LIN><<<dim3(4, (NN + BM - 1) / BM), 384, GEMM_SMEM>>>(
        x, NN, 0, bq, bk, bv, bs);

    attn_kernel<<<(NN * 32 + 255) / 256, 256>>>(hOut);

    // TA|TB = h @ [Wa Wb] + biases
    mma_gemm<DH><<<dim3(2, (NN + BM - 1) / BM), 384, GEMM_SMEM>>>(
        hOut, NN, 4, ba, bb, ba, ba);

    act_scores_kernel<<<(NN * 32 + 255) / 256, 256>>>(Wc, bc);
    softmax_stats_kernel<<<1, 1024>>>();
    output_kernel<<<512, 256>>>(lb, hOut, out);
}

// round 6
// speedup vs baseline: 2.8550x; 1.2111x over previous
#include <cuda_runtime.h>
#include <cuda_fp16.h>
#include <math.h>
#include <stdint.h>

#define NN 50000
#define NE 800000
#define LIN 1024
#define DH 256

// ===================== scratch (static device globals) =====================
__device__ float g_Q[(size_t)NN * DH];
__device__ __half g_Kh[(size_t)NN * DH];
__device__ float g_V[(size_t)NN * DH];
__device__ float g_S[(size_t)NN * DH];
__device__ float g_TA[(size_t)NN * DH];
__device__ float g_TB[(size_t)NN * DH];
__device__ float g_alpha[NE];
__device__ int   g_srcSorted[NE];
__device__ int   g_deg[NN];
__device__ int   g_off[NN + 1];
__device__ int   g_cur[NN];
__device__ float g_scores[NN * 2];
__device__ float g_cmax[2];
__device__ float g_csum[2];

// fp16 weights, transposed to [N=256, K] per matrix (k-major rows).
#define WBIG (256 * 1024)
#define WSML (256 * 256)
__device__ __half g_WH[4 * WBIG + 2 * WSML];

__device__ __forceinline__ float* out_sel(int s) {
    switch (s) {
        case 0: return g_Q;
        case 2: return g_V;
        case 3: return g_S;
        case 4: return g_TA;
        default: return g_TB;
    }
}

__device__ __forceinline__ float gelu_exact(float x) {
    return 0.5f * x * (1.0f + erff(x * 0.70710678118654752440f));
}

__device__ __forceinline__ uint32_t smem_u32(const void* p) {
    uint32_t a;
    asm("{ .reg .u64 t; cvta.to.shared.u64 t, %1; cvt.u32.u64 %0, t; }" : "=r"(a) : "l"(p));
    return a;
}

#define LDM_X4(r0, r1, r2, r3, addr) \
    asm volatile("ldmatrix.sync.aligned.m8n8.x4.shared.b16 {%0,%1,%2,%3}, [%4];" \
                 : "=r"(r0), "=r"(r1), "=r"(r2), "=r"(r3) : "r"(addr))

#define CP16(dst, src) \
    asm volatile("cp.async.cg.shared.global [%0], [%1], 16;" :: "r"(dst), "l"(src))

__device__ __forceinline__ void mma_f16(float* d, const uint32_t* a, const uint32_t* b) {
    asm volatile(
        "mma.sync.aligned.m16n8k16.row.col.f32.f16.f16.f32 "
        "{%0,%1,%2,%3},{%4,%5,%6,%7},{%8,%9},{%0,%1,%2,%3};"
        : "+f"(d[0]), "+f"(d[1]), "+f"(d[2]), "+f"(d[3])
        : "r"(a[0]), "r"(a[1]), "r"(a[2]), "r"(a[3]), "r"(b[0]), "r"(b[1]));
}

// ===================== init =====================
__global__ void init_kernel(float* __restrict__ out) {
    int i = blockIdx.x * blockDim.x + threadIdx.x;
    if (i < NN) g_deg[i] = 0;
    if (i < 512) out[i] = 0.0f;
}

// ===================== CSR build =====================
__global__ void count_kernel(const int* __restrict__ ei) {
    int e = blockIdx.x * blockDim.x + threadIdx.x;
    if (e < NE) atomicAdd(&g_deg[ei[NE + e]], 1);
}

__global__ void scan_kernel() {
    __shared__ int wsum[32];
    int tid = threadIdx.x, lane = tid & 31, w = tid >> 5;
    int carry = 0;
    for (int base = 0; base < NN; base += 1024) {
        int idx = base + tid;
        int v = (idx < NN) ? g_deg[idx] : 0;
        int x = v;
        #pragma unroll
        for (int o = 1; o < 32; o <<= 1) {
            int t = __shfl_up_sync(0xffffffffu, x, o);
            if (lane >= o) x += t;
        }
        if (lane == 31) wsum[w] = x;
        __syncthreads();
        if (w == 0) {
            int s = wsum[lane];
            #pragma unroll
            for (int o = 1; o < 32; o <<= 1) {
                int t = __shfl_up_sync(0xffffffffu, s, o);
                if (lane >= o) s += t;
            }
            wsum[lane] = s;
        }
        __syncthreads();
        int excl = x - v + (w ? wsum[w - 1] : 0) + carry;
        if (idx < NN) { g_off[idx] = excl; g_cur[idx] = excl; }
        int total = wsum[31];
        __syncthreads();
        carry += total;
    }
    if (tid == 0) g_off[NN] = carry;
}

__global__ void scatter_kernel(const int* __restrict__ ei) {
    int e = blockIdx.x * blockDim.x + threadIdx.x;
    if (e < NE) {
        int d = ei[NE + e];
        int p = atomicAdd(&g_cur[d], 1);
        g_srcSorted[p] = ei[e];
    }
}

// ===================== weight convert: W[K,256] -> [N=256,K] fp16 ==============
__global__ void conv_w_kernel(const float* __restrict__ Wq, const float* __restrict__ Wk,
                              const float* __restrict__ Wv, const float* __restrict__ Ws,
                              const float* __restrict__ Wa, const float* __restrict__ Wb) {
    int mat = blockIdx.y;
    int K = (mat < 4) ? 1024 : 256;
    size_t off = (mat < 4) ? (size_t)mat * WBIG : (size_t)4 * WBIG + (size_t)(mat - 4) * WSML;
    const float* W = (mat == 0) ? Wq : (mat == 1) ? Wk : (mat == 2) ? Wv :
                     (mat == 3) ? Ws : (mat == 4) ? Wa : Wb;
    int idx = blockIdx.x * blockDim.x + threadIdx.x;
    if (idx < 256 * K) {
        int n = idx / K, k = idx % K;
        g_WH[off + idx] = __float2half_rn(W[(size_t)k * 256 + n]);
    }
}

// ===================== HMMA GEMM (fp16 single product) =========================
// Block: 96(M) x 256(N), BK=32, 384 threads = 12 warps of 32x64.
// SMEM stage: AH[96][40] fp16, BH[256][40] fp16 (pad 40 elems/row)
#define AH_OFF 0
#define BH_OFF 7680
#define STAGE  28160
#define GEMM_SMEM (2 * STAGE)
#define BM 96

template <int KDIM>
__global__ __launch_bounds__(384, 1)
void mma_gemm(const float* __restrict__ X, int M, int matBase,
              const float* __restrict__ bias0, const float* __restrict__ bias1,
              const float* __restrict__ bias2, const float* __restrict__ bias3) {
    extern __shared__ char sm[];
    uint32_t smb = smem_u32(sm);
    int tid = threadIdx.x;
    int wid = tid >> 5;
    int lane = tid & 31;

    int mat = blockIdx.x;
    int m0 = blockIdx.y * BM;
    size_t wOff = (KDIM == 1024) ? (size_t)mat * WBIG
                                 : (size_t)4 * WBIG + (size_t)mat * WSML;
    const float* bias = (mat == 0) ? bias0 : (mat == 1) ? bias1 : (mat == 2) ? bias2 : bias3;
    bool toHalf = (matBase == 0 && mat == 1);
    float* Of = out_sel(matBase + mat);

    uint64_t gWH;
    {
        const __half* ph = g_WH + wOff;
        asm("cvta.to.global.u64 %0, %1;" : "=l"(gWH) : "l"(ph));
    }

    // A loader mapping: 96 rows x 32 cols fp32; tid -> row=tid>>2, q=tid&3 (8 cols)
    int ar = tid >> 2;
    int aq = tid & 3;
    int arow = m0 + ar;
    bool avalid = (arow < M);
    const float* aSrc = X + (size_t)arow * KDIM + aq * 8;

    // warp tiling: wm in {0,32,64}, wn in {0,64,128,192}
    int wm = (wid >> 2) * 32;
    int wn = (wid & 3) * 64;
    uint32_t a_row = (uint32_t)(wm + (lane & 7) + (lane & 8));
    uint32_t a_col = (uint32_t)((lane & 16) >> 1);
    uint32_t b_row = (uint32_t)(wn + ((lane & 16) >> 1) + (lane & 7));
    uint32_t b_col = (uint32_t)(lane & 8);

    float c[2][8][4];
    #pragma unroll
    for (int i = 0; i < 2; i++)
        #pragma unroll
        for (int j = 0; j < 8; j++)
            #pragma unroll
            for (int u = 0; u < 4; u++) c[i][j][u] = 0.0f;

    constexpr int T = KDIM / 32;
    float4 areg[2];

    // ---- B cp.async issue for chunk t into stage st ----
    auto issueB = [&](int t, int st) {
        uint32_t db = smb + (uint32_t)(st * STAGE);
        uint64_t koff = (uint64_t)t * 64;  // 32 halfs = 64 bytes
        for (int i = tid; i < 1024; i += 384) {
            int row = i >> 2, quad = i & 3;
            uint32_t d = db + BH_OFF + (uint32_t)row * 80u + (uint32_t)quad * 16u;
            CP16(d, gWH + (uint64_t)row * (KDIM * 2) + koff + quad * 16);
        }
        asm volatile("cp.async.commit_group;" ::: "memory");
    };

    auto ldA = [&](int t) {
        const float4 fz = make_float4(0.f, 0.f, 0.f, 0.f);
        const float* p = aSrc + t * 32;
        areg[0] = avalid ? ((const float4*)p)[0] : fz;
        areg[1] = avalid ? ((const float4*)p)[1] : fz;
    };

    auto stsA = [&](int st) {
        uint32_t h[8];
        float vv[8] = {areg[0].x, areg[0].y, areg[0].z, areg[0].w,
                       areg[1].x, areg[1].y, areg[1].z, areg[1].w};
        #pragma unroll
        for (int u = 0; u < 8; u++)
            h[u] = (uint32_t)__half_as_ushort(__float2half_rn(vv[u]));
        uint4 pk;
        pk.x = h[0] | (h[1] << 16); pk.y = h[2] | (h[3] << 16);
        pk.z = h[4] | (h[5] << 16); pk.w = h[6] | (h[7] << 16);
        *(uint4*)(sm + st * STAGE + AH_OFF + (size_t)ar * 80 + (size_t)aq * 16) = pk;
    };

    // ---- prologue ----
    issueB(0, 0);
    ldA(0);
    stsA(0);

    for (int t = 0; t < T; ++t) {
        int s = t & 1;
        asm volatile("cp.async.wait_group 0;" ::: "memory");
        __syncthreads();

        if (t + 1 < T) {
            issueB(t + 1, (t + 1) & 1);
            ldA(t + 1);
        }

        uint32_t sb = smb + (uint32_t)(s * STAGE);
        #pragma unroll
        for (int ks = 0; ks < 2; ks++) {
            uint32_t ahr[2][4];
            #pragma unroll
            for (int i = 0; i < 2; i++) {
                uint32_t off = (a_row + i * 16) * 80u + (ks * 16 + a_col) * 2u;
                LDM_X4(ahr[i][0], ahr[i][1], ahr[i][2], ahr[i][3], sb + AH_OFF + off);
            }
            uint32_t bhr[8][2];
            #pragma unroll
            for (int p = 0; p < 4; p++) {
                uint32_t off = (b_row + p * 16) * 80u + (ks * 16 + b_col) * 2u;
                LDM_X4(bhr[2 * p][0], bhr[2 * p][1], bhr[2 * p + 1][0], bhr[2 * p + 1][1],
                       sb + BH_OFF + off);
            }
            #pragma unroll
            for (int i = 0; i < 2; i++)
                #pragma unroll
                for (int j = 0; j < 8; j++) mma_f16(c[i][j], ahr[i], bhr[j]);
        }

        if (t + 1 < T) stsA((t + 1) & 1);
    }

    // ---- epilogue: bias + store ----
    #pragma unroll
    for (int i = 0; i < 2; i++) {
        int r0 = m0 + wm + i * 16 + (lane >> 2);
        int r1 = r0 + 8;
        #pragma unroll
        for (int j = 0; j < 8; j++) {
            int cc = wn + j * 8 + (lane & 3) * 2;
            float bx = bias[cc], by = bias[cc + 1];
            if (toHalf) {
                if (r0 < M)
                    *(__half2*)(g_Kh + (size_t)r0 * 256 + cc) =
                        __floats2half2_rn(c[i][j][0] + bx, c[i][j][1] + by);
                if (r1 < M)
                    *(__half2*)(g_Kh + (size_t)r1 * 256 + cc) =
                        __floats2half2_rn(c[i][j][2] + bx, c[i][j][3] + by);
            } else {
                if (r0 < M) {
                    float2 v = make_float2(c[i][j][0] + bx, c[i][j][1] + by);
                    *(float2*)(Of + (size_t)r0 * 256 + cc) = v;
                }
                if (r1 < M) {
                    float2 v = make_float2(c[i][j][2] + bx, c[i][j][3] + by);
                    *(float2*)(Of + (size_t)r1 * 256 + cc) = v;
                }
            }
        }
    }
}

// ===================== fused edge softmax + aggregation + residual + gelu ======
__global__ __launch_bounds__(256)
void attn_kernel(float* __restrict__ hOut) {
    int warp = (blockIdx.x * blockDim.x + threadIdx.x) >> 5;
    int lane = threadIdx.x & 31;
    if (warp >= NN) return;
    int d = warp;

    const float4* Qr = (const float4*)(g_Q + (size_t)d * 256);
    float4 q0 = Qr[2 * lane], q1 = Qr[2 * lane + 1];
    int e0 = g_off[d], e1 = g_off[d + 1];

    float amax = -INFINITY;
    for (int e = e0; e < e1; ++e) {
        int s = g_srcSorted[e];
        uint4 kk = *(const uint4*)(g_Kh + (size_t)s * 256 + lane * 8);
        float2 k0 = __half22float2(*(__half2*)&kk.x);
        float2 k1 = __half22float2(*(__half2*)&kk.y);
        float2 k2 = __half22float2(*(__half2*)&kk.z);
        float2 k3 = __half22float2(*(__half2*)&kk.w);
        float dot = q0.x * k0.x + q0.y * k0.y + q0.z * k1.x + q0.w * k1.y
                  + q1.x * k2.x + q1.y * k2.y + q1.z * k3.x + q1.w * k3.y;
        #pragma unroll
        for (int o = 16; o; o >>= 1) dot += __shfl_xor_sync(0xffffffffu, dot, o);
        dot *= 0.0625f;
        g_alpha[e] = dot;
        amax = fmaxf(amax, dot);
    }

    float den = 0.0f;
    float4 acc0 = make_float4(0, 0, 0, 0), acc1 = make_float4(0, 0, 0, 0);
    for (int e = e0; e < e1; ++e) {
        float w = expf(g_alpha[e] - amax);
        den += w;
        int s = g_srcSorted[e];
        const float4* Vr = (const float4*)(g_V + (size_t)s * 256);
        float4 v0 = Vr[2 * lane], v1 = Vr[2 * lane + 1];
        acc0.x += w * v0.x; acc0.y += w * v0.y; acc0.z += w * v0.z; acc0.w += w * v0.w;
        acc1.x += w * v1.x; acc1.y += w * v1.y; acc1.z += w * v1.z; acc1.w += w * v1.w;
    }
    float inv = 1.0f / (den + 1e-16f);

    const float4* Sr = (const float4*)(g_S + (size_t)d * 256);
    float4 s0 = Sr[2 * lane], s1 = Sr[2 * lane + 1];
    float4 h0, h1;
    h0.x = gelu_exact(acc0.x * inv + s0.x);
    h0.y = gelu_exact(acc0.y * inv + s0.y);
    h0.z = gelu_exact(acc0.z * inv + s0.z);
    h0.w = gelu_exact(acc0.w * inv + s0.w);
    h1.x = gelu_exact(acc1.x * inv + s1.x);
    h1.y = gelu_exact(acc1.y * inv + s1.y);
    h1.z = gelu_exact(acc1.z * inv + s1.z);
    h1.w = gelu_exact(acc1.w * inv + s1.w);

    float4* Hr = (float4*)(hOut + (size_t)d * 256);
    Hr[2 * lane] = h0;
    Hr[2 * lane + 1] = h1;
}

// ===================== gate + scores =====================
__global__ __launch_bounds__(256)
void act_scores_kernel(const float* __restrict__ Wc, const float* __restrict__ bc) {
    int warp = (blockIdx.x * blockDim.x + threadIdx.x) >> 5;
    int lane = threadIdx.x & 31;
    if (warp >= NN) return;
    int n = warp;

    const float4* Ar = (const float4*)(g_TA + (size_t)n * 256);
    const float4* Br = (const float4*)(g_TB + (size_t)n * 256);
    float s0 = 0.0f, s1 = 0.0f;
    #pragma unroll
    for (int part = 0; part < 2; part++) {
        int idx = 2 * lane + part;
        float4 av = Ar[idx], bv = Br[idx];
        float aa[4] = {av.x, av.y, av.z, av.w};
        float bb[4] = {bv.x, bv.y, bv.z, bv.w};
        int jbase = idx * 4;
        #pragma unroll
        for (int u = 0; u < 4; u++) {
            float a = tanhf(aa[u]);
            float b = 1.0f / (1.0f + expf(-bb[u]));
            float g = a * b;
            s0 += g * Wc[(jbase + u) * 2 + 0];
            s1 += g * Wc[(jbase + u) * 2 + 1];
        }
    }
    #pragma unroll
    for (int o = 16; o; o >>= 1) {
        s0 += __shfl_xor_sync(0xffffffffu, s0, o);
        s1 += __shfl_xor_sync(0xffffffffu, s1, o);
    }
    if (lane == 0) {
        g_scores[2 * n + 0] = s0 + bc[0];
        g_scores[2 * n + 1] = s1 + bc[1];
    }
}

// ===================== column softmax stats =====================
__global__ void softmax_stats_kernel() {
    __shared__ float sh[1024];
    int tid = threadIdx.x;
    float m0 = -INFINITY, m1 = -INFINITY;
    for (int i = tid; i < NN; i += 1024) {
        m0 = fmaxf(m0, g_scores[2 * i]);
        m1 = fmaxf(m1, g_scores[2 * i + 1]);
    }
    sh[tid] = m0; __syncthreads();
    for (int o = 512; o; o >>= 1) { if (tid < o) sh[tid] = fmaxf(sh[tid], sh[tid + o]); __syncthreads(); }
    float cm0 = sh[0]; __syncthreads();
    sh[tid] = m1; __syncthreads();
    for (int o = 512; o; o >>= 1) { if (tid < o) sh[tid] = fmaxf(sh[tid], sh[tid + o]); __syncthreads(); }
    float cm1 = sh[0]; __syncthreads();

    float s0 = 0.0f, s1 = 0.0f;
    for (int i = tid; i < NN; i += 1024) {
        s0 += expf(g_scores[2 * i] - cm0);
        s1 += expf(g_scores[2 * i + 1] - cm1);
    }
    sh[tid] = s0; __syncthreads();
    for (int o = 512; o; o >>= 1) { if (tid < o) sh[tid] += sh[tid + o]; __syncthreads(); }
    float sum0 = sh[0]; __syncthreads();
    sh[tid] = s1; __syncthreads();
    for (int o = 512; o; o >>= 1) { if (tid < o) sh[tid] += sh[tid + o]; __syncthreads(); }
    float sum1 = sh[0];
    if (tid == 0) {
        g_cmax[0] = cm0; g_cmax[1] = cm1;
        g_csum[0] = sum0; g_csum[1] = sum1;
    }
}

// ===================== attn output, A, y = attn.T @ h =====================
__global__ __launch_bounds__(256)
void output_kernel(const int* __restrict__ label,
                   const float* __restrict__ h,
                   float* __restrict__ out) {
    int t = threadIdx.x;
    float cm0 = g_cmax[0], cm1 = g_cmax[1];
    float is0 = 1.0f / g_csum[0], is1 = 1.0f / g_csum[1];
    int lbl = *label;
    float y0 = 0.0f, y1 = 0.0f;
    for (int n = blockIdx.x; n < NN; n += gridDim.x) {
        float sc0 = g_scores[2 * n], sc1 = g_scores[2 * n + 1];
        float a0 = expf(sc0 - cm0) * is0;
        float a1 = expf(sc1 - cm1) * is1;
        if (t == 0) out[512 + n] = (lbl == 0) ? a0 : a1;
        float hv = h[(size_t)n * 256 + t];
        y0 += a0 * hv;
        y1 += a1 * hv;
    }
    atomicAdd(&out[t], y0);
    atomicAdd(&out[256 + t], y1);
}

// ===================== launch =====================
extern "C" void kernel_launch(void* const* d_in, const int* in_sizes, int n_in,
                              void* d_out, int out_size) {
    const float* x  = (const float*)d_in[0];
    const float* Wq = (const float*)d_in[1];  const float* bq = (const float*)d_in[2];
    const float* Wk = (const float*)d_in[3];  const float* bk = (const float*)d_in[4];
    const float* Wv = (const float*)d_in[5];  const float* bv = (const float*)d_in[6];
    const float* Ws = (const float*)d_in[7];  const float* bs = (const float*)d_in[8];
    const float* Wa = (const float*)d_in[9];  const float* ba = (const float*)d_in[10];
    const float* Wb = (const float*)d_in[11]; const float* bb = (const float*)d_in[12];
    const float* Wc = (const float*)d_in[13]; const float* bc = (const float*)d_in[14];
    const int*   ei = (const int*)d_in[15];
    const int*   lb = (const int*)d_in[16];

    float* out  = (float*)d_out;
    float* hOut = out + 512 + NN;

    cudaFuncSetAttribute(mma_gemm<LIN>, cudaFuncAttributeMaxDynamicSharedMemorySize, GEMM_SMEM);
    cudaFuncSetAttribute(mma_gemm<DH>,  cudaFuncAttributeMaxDynamicSharedMemorySize, GEMM_SMEM);

    init_kernel<<<(NN + 255) / 256, 256>>>(out);
    count_kernel<<<(NE + 255) / 256, 256>>>(ei);
    scan_kernel<<<1, 1024>>>();
    scatter_kernel<<<(NE + 255) / 256, 256>>>(ei);

    conv_w_kernel<<<dim3((256 * 1024 + 255) / 256, 6), 256>>>(Wq, Wk, Wv, Ws, Wa, Wb);

    // Q|K|V|S = x @ [Wq Wk Wv Ws] + biases  (HMMA fp16 single product)
    mma_gemm<LIN><<<dim3(4, (NN + BM - 1) / BM), 384, GEMM_SMEM>>>(
        x, NN, 0, bq, bk, bv, bs);

    attn_kernel<<<(NN * 32 + 255) / 256, 256>>>(hOut);

    // TA|TB = h @ [Wa Wb] + biases
    mma_gemm<DH><<<dim3(2, (NN + BM - 1) / BM), 384, GEMM_SMEM>>>(
        hOut, NN, 4, ba, bb, ba, ba);

    act_scores_kernel<<<(NN * 32 + 255) / 256, 256>>>(Wc, bc);
    softmax_stats_kernel<<<1, 1024>>>();
    output_kernel<<<512, 256>>>(lb, hOut, out);
}

// round 9
// speedup vs baseline: 3.3609x; 1.1772x over previous
#include <cuda_runtime.h>
#include <cuda_fp16.h>
#include <math.h>
#include <stdint.h>

#define NN 50000
#define NE 800000
#define LIN 1024
#define DH 256

// ===================== scratch (static device globals) =====================
__device__ __half g_Xh[(size_t)NN * LIN];   // fp16 copy of x
__device__ float  g_Q[(size_t)NN * DH];
__device__ __half g_Kh[(size_t)NN * DH];
__device__ __half g_Vh[(size_t)NN * DH];
__device__ float  g_S[(size_t)NN * DH];
__device__ __half g_Hh[(size_t)NN * DH];    // fp16 copy of h (for GEMM2 A side)
__device__ float  g_TA[(size_t)NN * DH];
__device__ float  g_TB[(size_t)NN * DH];
__device__ float  g_alpha[NE];
__device__ int    g_srcSorted[NE];
__device__ int    g_deg[NN];
__device__ int    g_off[NN + 1];
__device__ int    g_cur[NN];
__device__ float  g_scores[NN * 2];
__device__ float  g_cmax[2];
__device__ float  g_csum[2];

// fp16 weights, transposed to [N=256, K] per matrix (k-major rows).
#define WBIG (256 * 1024)
#define WSML (256 * 256)
__device__ __half g_WH[4 * WBIG + 2 * WSML];

__device__ __forceinline__ float gelu_exact(float x) {
    return 0.5f * x * (1.0f + erff(x * 0.70710678118654752440f));
}

__device__ __forceinline__ uint32_t smem_u32(const void* p) {
    uint32_t a;
    asm("{ .reg .u64 t; cvta.to.shared.u64 t, %1; cvt.u32.u64 %0, t; }" : "=r"(a) : "l"(p));
    return a;
}

#define LDM_X4(r0, r1, r2, r3, addr) \
    asm volatile("ldmatrix.sync.aligned.m8n8.x4.shared.b16 {%0,%1,%2,%3}, [%4];" \
                 : "=r"(r0), "=r"(r1), "=r"(r2), "=r"(r3) : "r"(addr))

#define CP16(dst, src) \
    asm volatile("cp.async.cg.shared.global [%0], [%1], 16;" :: "r"(dst), "l"(src))

__device__ __forceinline__ void mma_f16(float* d, const uint32_t* a, const uint32_t* b) {
    asm volatile(
        "mma.sync.aligned.m16n8k16.row.col.f32.f16.f16.f32 "
        "{%0,%1,%2,%3},{%4,%5,%6,%7},{%8,%9},{%0,%1,%2,%3};"
        : "+f"(d[0]), "+f"(d[1]), "+f"(d[2]), "+f"(d[3])
        : "r"(a[0]), "r"(a[1]), "r"(a[2]), "r"(a[3]), "r"(b[0]), "r"(b[1]));
}

// ===================== init =====================
__global__ void init_kernel(float* __restrict__ out) {
    int i = blockIdx.x * blockDim.x + threadIdx.x;
    if (i < NN) g_deg[i] = 0;
    if (i < 512) out[i] = 0.0f;
}

// ===================== CSR build =====================
__global__ void count_kernel(const int* __restrict__ ei) {
    int e = blockIdx.x * blockDim.x + threadIdx.x;
    if (e < NE) atomicAdd(&g_deg[ei[NE + e]], 1);
}

__global__ void scan_kernel() {
    __shared__ int wsum[32];
    int tid = threadIdx.x, lane = tid & 31, w = tid >> 5;
    int carry = 0;
    for (int base = 0; base < NN; base += 1024) {
        int idx = base + tid;
        int v = (idx < NN) ? g_deg[idx] : 0;
        int x = v;
        #pragma unroll
        for (int o = 1; o < 32; o <<= 1) {
            int t = __shfl_up_sync(0xffffffffu, x, o);
            if (lane >= o) x += t;
        }
        if (lane == 31) wsum[w] = x;
        __syncthreads();
        if (w == 0) {
            int s = wsum[lane];
            #pragma unroll
            for (int o = 1; o < 32; o <<= 1) {
                int t = __shfl_up_sync(0xffffffffu, s, o);
                if (lane >= o) s += t;
            }
            wsum[lane] = s;
        }
        __syncthreads();
        int excl = x - v + (w ? wsum[w - 1] : 0) + carry;
        if (idx < NN) { g_off[idx] = excl; g_cur[idx] = excl; }
        int total = wsum[31];
        __syncthreads();
        carry += total;
    }
    if (tid == 0) g_off[NN] = carry;
}

__global__ void scatter_kernel(const int* __restrict__ ei) {
    int e = blockIdx.x * blockDim.x + threadIdx.x;
    if (e < NE) {
        int d = ei[NE + e];
        int p = atomicAdd(&g_cur[d], 1);
        g_srcSorted[p] = ei[e];
    }
}

// ===================== weight convert: W[K,256] -> [N=256,K] fp16 ==============
__global__ void conv_w_kernel(const float* __restrict__ Wq, const float* __restrict__ Wk,
                              const float* __restrict__ Wv, const float* __restrict__ Ws,
                              const float* __restrict__ Wa, const float* __restrict__ Wb) {
    int mat = blockIdx.y;
    int K = (mat < 4) ? 1024 : 256;
    size_t off = (mat < 4) ? (size_t)mat * WBIG : (size_t)4 * WBIG + (size_t)(mat - 4) * WSML;
    const float* W = (mat == 0) ? Wq : (mat == 1) ? Wk : (mat == 2) ? Wv :
                     (mat == 3) ? Ws : (mat == 4) ? Wa : Wb;
    int idx = blockIdx.x * blockDim.x + threadIdx.x;
    if (idx < 256 * K) {
        int n = idx / K, k = idx % K;
        g_WH[off + idx] = __float2half_rn(W[(size_t)k * 256 + n]);
    }
}

// ===================== x convert: fp32 -> fp16 (vectorized) ====================
__global__ void conv_x_kernel(const float* __restrict__ X) {
    size_t i = ((size_t)blockIdx.x * blockDim.x + threadIdx.x) * 8;
    if (i < (size_t)NN * LIN) {
        float4 a = *(const float4*)(X + i);
        float4 b = *(const float4*)(X + i + 4);
        uint4 pk;
        __half2 h0 = __floats2half2_rn(a.x, a.y);
        __half2 h1 = __floats2half2_rn(a.z, a.w);
        __half2 h2 = __floats2half2_rn(b.x, b.y);
        __half2 h3 = __floats2half2_rn(b.z, b.w);
        pk.x = *(uint32_t*)&h0; pk.y = *(uint32_t*)&h1;
        pk.z = *(uint32_t*)&h2; pk.w = *(uint32_t*)&h3;
        *(uint4*)(g_Xh + i) = pk;
    }
}

// ===================== HMMA GEMM (fp16, pure cp.async, 4-stage) ================
// Block: 96(M) x 256(N), BK=32, 384 threads = 12 warps of 32x64.
// SMEM stage: A[96][40] fp16, B[256][40] fp16 (pad 40 elems/row)
#define AH_OFF 0
#define BH_OFF 7680
#define STAGE  28160
#define NSTAGE 4
#define GEMM_SMEM (NSTAGE * STAGE)
#define BM 96

template <int KDIM>
__global__ __launch_bounds__(384, 1)
void mma_gemm(const __half* __restrict__ Ah, int M, int matBase,
              const float* __restrict__ bias0, const float* __restrict__ bias1,
              const float* __restrict__ bias2, const float* __restrict__ bias3) {
    extern __shared__ char sm[];
    uint32_t smb = smem_u32(sm);
    int tid = threadIdx.x;
    int wid = tid >> 5;
    int lane = tid & 31;

    int mat = blockIdx.x;
    int m0 = blockIdx.y * BM;
    size_t wOff = (KDIM == 1024) ? (size_t)mat * WBIG
                                 : (size_t)4 * WBIG + (size_t)mat * WSML;
    const float* bias = (mat == 0) ? bias0 : (mat == 1) ? bias1 : (mat == 2) ? bias2 : bias3;
    // output kind: 0 = fp32 buffer, 1 = g_Kh, 2 = g_Vh
    int outKind = (matBase == 0 && mat == 1) ? 1 : (matBase == 0 && mat == 2) ? 2 : 0;
    float* Of = (matBase == 0) ? ((mat == 0) ? g_Q : g_S)
                               : ((mat == 0) ? g_TA : g_TB);

    uint64_t gW, gA;
    {
        const __half* pw = g_WH + wOff;
        asm("cvta.to.global.u64 %0, %1;" : "=l"(gW) : "l"(pw));
        int rowA = m0 + (tid >> 2);
        if (rowA >= M) rowA = M - 1;
        const __half* pa = Ah + (size_t)rowA * KDIM + (tid & 3) * 8;
        asm("cvta.to.global.u64 %0, %1;" : "=l"(gA) : "l"(pa));
    }
    uint32_t aDst = (uint32_t)(tid >> 2) * 80u + (uint32_t)(tid & 3) * 16u;

    // warp tiling: wm in {0,32,64}, wn in {0,64,128,192}
    int wm = (wid >> 2) * 32;
    int wn = (wid & 3) * 64;
    uint32_t a_row = (uint32_t)(wm + (lane & 7) + (lane & 8));
    uint32_t a_col = (uint32_t)((lane & 16) >> 1);
    uint32_t b_row = (uint32_t)(wn + ((lane & 16) >> 1) + (lane & 7));
    uint32_t b_col = (uint32_t)(lane & 8);

    float c[2][8][4];
    #pragma unroll
    for (int i = 0; i < 2; i++)
        #pragma unroll
        for (int j = 0; j < 8; j++)
            #pragma unroll
            for (int u = 0; u < 4; u++) c[i][j][u] = 0.0f;

    constexpr int T = KDIM / 32;

    // ---- issue A+B cp.async for chunk t into stage t&3 ----
    auto issue = [&](int t) {
        uint32_t db = smb + (uint32_t)((t & 3) * STAGE);
        uint64_t koff = (uint64_t)t * 64;  // 32 halfs = 64 bytes
        CP16(db + AH_OFF + aDst, gA + koff);
        for (int i = tid; i < 1024; i += 384) {
            int row = i >> 2, quad = i & 3;
            uint32_t d = db + BH_OFF + (uint32_t)row * 80u + (uint32_t)quad * 16u;
            CP16(d, gW + (uint64_t)row * (KDIM * 2) + koff + quad * 16);
        }
        asm volatile("cp.async.commit_group;" ::: "memory");
    };

    // ---- prologue: fill 3 stages ----
    issue(0);
    issue(1);
    issue(2);

    for (int t = 0; t < T; ++t) {
        if (t + 3 < T)      { asm volatile("cp.async.wait_group 2;" ::: "memory"); }
        else if (t + 2 < T) { asm volatile("cp.async.wait_group 1;" ::: "memory"); }
        else                { asm volatile("cp.async.wait_group 0;" ::: "memory"); }
        __syncthreads();

        if (t + 3 < T) issue(t + 3);

        uint32_t sb = smb + (uint32_t)((t & 3) * STAGE);
        #pragma unroll
        for (int ks = 0; ks < 2; ks++) {
            uint32_t ahr[2][4];
            #pragma unroll
            for (int i = 0; i < 2; i++) {
                uint32_t off = (a_row + i * 16) * 80u + (ks * 16 + a_col) * 2u;
                LDM_X4(ahr[i][0], ahr[i][1], ahr[i][2], ahr[i][3], sb + AH_OFF + off);
            }
            uint32_t bhr[8][2];
            #pragma unroll
            for (int p = 0; p < 4; p++) {
                uint32_t off = (b_row + p * 16) * 80u + (ks * 16 + b_col) * 2u;
                LDM_X4(bhr[2 * p][0], bhr[2 * p][1], bhr[2 * p + 1][0], bhr[2 * p + 1][1],
                       sb + BH_OFF + off);
            }
            #pragma unroll
            for (int i = 0; i < 2; i++)
                #pragma unroll
                for (int j = 0; j < 8; j++) mma_f16(c[i][j], ahr[i], bhr[j]);
        }
    }

    // ---- epilogue: bias + store ----
    #pragma unroll
    for (int i = 0; i < 2; i++) {
        int r0 = m0 + wm + i * 16 + (lane >> 2);
        int r1 = r0 + 8;
        #pragma unroll
        for (int j = 0; j < 8; j++) {
            int cc = wn + j * 8 + (lane & 3) * 2;
            float bx = bias[cc], by = bias[cc + 1];
            if (outKind) {
                __half* H = (outKind == 1) ? g_Kh : g_Vh;
                if (r0 < M)
                    *(__half2*)(H + (size_t)r0 * 256 + cc) =
                        __floats2half2_rn(c[i][j][0] + bx, c[i][j][1] + by);
                if (r1 < M)
                    *(__half2*)(H + (size_t)r1 * 256 + cc) =
                        __floats2half2_rn(c[i][j][2] + bx, c[i][j][3] + by);
            } else {
                if (r0 < M) {
                    float2 v = make_float2(c[i][j][0] + bx, c[i][j][1] + by);
                    *(float2*)(Of + (size_t)r0 * 256 + cc) = v;
                }
                if (r1 < M) {
                    float2 v = make_float2(c[i][j][2] + bx, c[i][j][3] + by);
                    *(float2*)(Of + (size_t)r1 * 256 + cc) = v;
                }
            }
        }
    }
}

// ===================== fused edge softmax + aggregation + residual + gelu ======
__global__ __launch_bounds__(256)
void attn_kernel(float* __restrict__ hOut) {
    int warp = (blockIdx.x * blockDim.x + threadIdx.x) >> 5;
    int lane = threadIdx.x & 31;
    if (warp >= NN) return;
    int d = warp;

    const float4* Qr = (const float4*)(g_Q + (size_t)d * 256);
    float4 q0 = Qr[2 * lane], q1 = Qr[2 * lane + 1];
    int e0 = g_off[d], e1 = g_off[d + 1];

    float amax = -INFINITY;
    for (int e = e0; e < e1; ++e) {
        int s = g_srcSorted[e];
        uint4 kk = *(const uint4*)(g_Kh + (size_t)s * 256 + lane * 8);
        float2 k0 = __half22float2(*(__half2*)&kk.x);
        float2 k1 = __half22float2(*(__half2*)&kk.y);
        float2 k2 = __half22float2(*(__half2*)&kk.z);
        float2 k3 = __half22float2(*(__half2*)&kk.w);
        float dot = q0.x * k0.x + q0.y * k0.y + q0.z * k1.x + q0.w * k1.y
                  + q1.x * k2.x + q1.y * k2.y + q1.z * k3.x + q1.w * k3.y;
        #pragma unroll
        for (int o = 16; o; o >>= 1) dot += __shfl_xor_sync(0xffffffffu, dot, o);
        dot *= 0.0625f;
        g_alpha[e] = dot;
        amax = fmaxf(amax, dot);
    }

    float den = 0.0f;
    float acc[8] = {0, 0, 0, 0, 0, 0, 0, 0};
    for (int e = e0; e < e1; ++e) {
        float w = expf(g_alpha[e] - amax);
        den += w;
        int s = g_srcSorted[e];
        uint4 vv = *(const uint4*)(g_Vh + (size_t)s * 256 + lane * 8);
        float2 v0 = __half22float2(*(__half2*)&vv.x);
        float2 v1 = __half22float2(*(__half2*)&vv.y);
        float2 v2 = __half22float2(*(__half2*)&vv.z);
        float2 v3 = __half22float2(*(__half2*)&vv.w);
        acc[0] += w * v0.x; acc[1] += w * v0.y;
        acc[2] += w * v1.x; acc[3] += w * v1.y;
        acc[4] += w * v2.x; acc[5] += w * v2.y;
        acc[6] += w * v3.x; acc[7] += w * v3.y;
    }
    float inv = 1.0f / (den + 1e-16f);

    const float4* Sr = (const float4*)(g_S + (size_t)d * 256);
    float4 s0 = Sr[2 * lane], s1 = Sr[2 * lane + 1];
    float sv[8] = {s0.x, s0.y, s0.z, s0.w, s1.x, s1.y, s1.z, s1.w};
    float hv[8];
    #pragma unroll
    for (int u = 0; u < 8; u++) hv[u] = gelu_exact(acc[u] * inv + sv[u]);

    float4* Hr = (float4*)(hOut + (size_t)d * 256);
    Hr[2 * lane]     = make_float4(hv[0], hv[1], hv[2], hv[3]);
    Hr[2 * lane + 1] = make_float4(hv[4], hv[5], hv[6], hv[7]);

    __half2 p0 = __floats2half2_rn(hv[0], hv[1]);
    __half2 p1 = __floats2half2_rn(hv[2], hv[3]);
    __half2 p2 = __floats2half2_rn(hv[4], hv[5]);
    __half2 p3 = __floats2half2_rn(hv[6], hv[7]);
    uint4 pk;
    pk.x = *(uint32_t*)&p0; pk.y = *(uint32_t*)&p1;
    pk.z = *(uint32_t*)&p2; pk.w = *(uint32_t*)&p3;
    *(uint4*)(g_Hh + (size_t)d * 256 + lane * 8) = pk;
}

// ===================== gate + scores =====================
__global__ __launch_bounds__(256)
void act_scores_kernel(const float* __restrict__ Wc, const float* __restrict__ bc) {
    int warp = (blockIdx.x * blockDim.x + threadIdx.x) >> 5;
    int lane = threadIdx.x & 31;
    if (warp >= NN) return;
    int n = warp;

    const float4* Ar = (const float4*)(g_TA + (size_t)n * 256);
    const float4* Br = (const float4*)(g_TB + (size_t)n * 256);
    float s0 = 0.0f, s1 = 0.0f;
    #pragma unroll
    for (int part = 0; part < 2; part++) {
        int idx = 2 * lane + part;
        float4 av = Ar[idx], bv = Br[idx];
        float aa[4] = {av.x, av.y, av.z, av.w};
        float bb[4] = {bv.x, bv.y, bv.z, bv.w};
        int jbase = idx * 4;
        #pragma unroll
        for (int u = 0; u < 4; u++) {
            float a = tanhf(aa[u]);
            float b = 1.0f / (1.0f + expf(-bb[u]));
            float g = a * b;
            s0 += g * Wc[(jbase + u) * 2 + 0];
            s1 += g * Wc[(jbase + u) * 2 + 1];
        }
    }
    #pragma unroll
    for (int o = 16; o; o >>= 1) {
        s0 += __shfl_xor_sync(0xffffffffu, s0, o);
        s1 += __shfl_xor_sync(0xffffffffu, s1, o);
    }
    if (lane == 0) {
        g_scores[2 * n + 0] = s0 + bc[0];
        g_scores[2 * n + 1] = s1 + bc[1];
    }
}

// ===================== column softmax stats =====================
__global__ void softmax_stats_kernel() {
    __shared__ float sh[1024];
    int tid = threadIdx.x;
    float m0 = -INFINITY, m1 = -INFINITY;
    for (int i = tid; i < NN; i += 1024) {
        m0 = fmaxf(m0, g_scores[2 * i]);
        m1 = fmaxf(m1, g_scores[2 * i + 1]);
    }
    sh[tid] = m0; __syncthreads();
    for (int o = 512; o; o >>= 1) { if (tid < o) sh[tid] = fmaxf(sh[tid], sh[tid + o]); __syncthreads(); }
    float cm0 = sh[0]; __syncthreads();
    sh[tid] = m1; __syncthreads();
    for (int o = 512; o; o >>= 1) { if (tid < o) sh[tid] = fmaxf(sh[tid], sh[tid + o]); __syncthreads(); }
    float cm1 = sh[0]; __syncthreads();

    float s0 = 0.0f, s1 = 0.0f;
    for (int i = tid; i < NN; i += 1024) {
        s0 += expf(g_scores[2 * i] - cm0);
        s1 += expf(g_scores[2 * i + 1] - cm1);
    }
    sh[tid] = s0; __syncthreads();
    for (int o = 512; o; o >>= 1) { if (tid < o) sh[tid] += sh[tid + o]; __syncthreads(); }
    float sum0 = sh[0]; __syncthreads();
    sh[tid] = s1; __syncthreads();
    for (int o = 512; o; o >>= 1) { if (tid < o) sh[tid] += sh[tid + o]; __syncthreads(); }
    float sum1 = sh[0];
    if (tid == 0) {
        g_cmax[0] = cm0; g_cmax[1] = cm1;
        g_csum[0] = sum0; g_csum[1] = sum1;
    }
}

// ===================== attn output, A, y = attn.T @ h =====================
__global__ __launch_bounds__(256)
void output_kernel(const int* __restrict__ label,
                   const float* __restrict__ h,
                   float* __restrict__ out) {
    int t = threadIdx.x;
    float cm0 = g_cmax[0], cm1 = g_cmax[1];
    float is0 = 1.0f / g_csum[0], is1 = 1.0f / g_csum[1];
    int lbl = *label;
    float y0 = 0.0f, y1 = 0.0f;
    for (int n = blockIdx.x; n < NN; n += gridDim.x) {
        float sc0 = g_scores[2 * n], sc1 = g_scores[2 * n + 1];
        float a0 = expf(sc0 - cm0) * is0;
        float a1 = expf(sc1 - cm1) * is1;
        if (t == 0) out[512 + n] = (lbl == 0) ? a0 : a1;
        float hv = h[(size_t)n * 256 + t];
        y0 += a0 * hv;
        y1 += a1 * hv;
    }
    atomicAdd(&out[t], y0);
    atomicAdd(&out[256 + t], y1);
}

// ===================== launch =====================
extern "C" void kernel_launch(void* const* d_in, const int* in_sizes, int n_in,
                              void* d_out, int out_size) {
    const float* x  = (const float*)d_in[0];
    const float* Wq = (const float*)d_in[1];  const float* bq = (const float*)d_in[2];
    const float* Wk = (const float*)d_in[3];  const float* bk = (const float*)d_in[4];
    const float* Wv = (const float*)d_in[5];  const float* bv = (const float*)d_in[6];
    const float* Ws = (const float*)d_in[7];  const float* bs = (const float*)d_in[8];
    const float* Wa = (const float*)d_in[9];  const float* ba = (const float*)d_in[10];
    const float* Wb = (const float*)d_in[11]; const float* bb = (const float*)d_in[12];
    const float* Wc = (const float*)d_in[13]; const float* bc = (const float*)d_in[14];
    const int*   ei = (const int*)d_in[15];
    const int*   lb = (const int*)d_in[16];

    float* out  = (float*)d_out;
    float* hOut = out + 512 + NN;

    cudaFuncSetAttribute(mma_gemm<LIN>, cudaFuncAttributeMaxDynamicSharedMemorySize, GEMM_SMEM);
    cudaFuncSetAttribute(mma_gemm<DH>,  cudaFuncAttributeMaxDynamicSharedMemorySize, GEMM_SMEM);

    init_kernel<<<(NN + 255) / 256, 256>>>(out);
    count_kernel<<<(NE + 255) / 256, 256>>>(ei);
    scan_kernel<<<1, 1024>>>();
    scatter_kernel<<<(NE + 255) / 256, 256>>>(ei);

    conv_w_kernel<<<dim3((256 * 1024 + 255) / 256, 6), 256>>>(Wq, Wk, Wv, Ws, Wa, Wb);
    conv_x_kernel<<<((NN * (size_t)LIN / 8) + 255) / 256, 256>>>(x);

    // Q|K|V|S = x @ [Wq Wk Wv Ws] + biases
    {
        __half* xh;
        cudaGetSymbolAddress((void**)&xh, g_Xh);
        mma_gemm<LIN><<<dim3(4, (NN + BM - 1) / BM), 384, GEMM_SMEM>>>(
            xh, NN, 0, bq, bk, bv, bs);
    }

    attn_kernel<<<(NN * 32 + 255) / 256, 256>>>(hOut);

    // TA|TB = h @ [Wa Wb] + biases
    {
        __half* hh;
        cudaGetSymbolAddress((void**)&hh, g_Hh);
        mma_gemm<DH><<<dim3(2, (NN + BM - 1) / BM), 384, GEMM_SMEM>>>(
            hh, NN, 4, ba, bb, ba, ba);
    }

    act_scores_kernel<<<(NN * 32 + 255) / 256, 256>>>(Wc, bc);
    softmax_stats_kernel<<<1, 1024>>>();
    output_kernel<<<512, 256>>>(lb, hOut, out);
}

// round 11
// speedup vs baseline: 3.6316x; 1.0806x over previous
#include <cuda_runtime.h>
#include <cuda_fp16.h>
#include <math.h>
#include <stdint.h>

#define NN 50000
#define NE 800000
#define LIN 1024
#define DH 256

// ===================== scratch (static device globals) =====================
__device__ __half g_Xh[(size_t)NN * LIN];   // fp16 copy of x
__device__ __half g_Qh[(size_t)NN * DH];
__device__ __half g_Kh[(size_t)NN * DH];
__device__ __half g_Vh[(size_t)NN * DH];
__device__ __half g_Sh[(size_t)NN * DH];
__device__ __half g_Hh[(size_t)NN * DH];    // fp16 copy of h (for GEMM2 A side)
__device__ float  g_TA[(size_t)NN * DH];
__device__ float  g_TB[(size_t)NN * DH];
__device__ float  g_alpha[NE];
__device__ int    g_srcSorted[NE];
__device__ int    g_deg[NN];
__device__ int    g_off[NN + 1];
__device__ int    g_cur[NN];
__device__ float  g_scores[NN * 2];
__device__ float  g_cmax[2];
__device__ float  g_csum[2];

// fp16 weights, transposed to [N=256, K] per matrix (k-major rows).
#define WBIG (256 * 1024)
#define WSML (256 * 256)
__device__ __half g_WH[4 * WBIG + 2 * WSML];

__device__ __forceinline__ float gelu_exact(float x) {
    return 0.5f * x * (1.0f + erff(x * 0.70710678118654752440f));
}

__device__ __forceinline__ uint32_t smem_u32(const void* p) {
    uint32_t a;
    asm("{ .reg .u64 t; cvta.to.shared.u64 t, %1; cvt.u32.u64 %0, t; }" : "=r"(a) : "l"(p));
    return a;
}

#define LDM_X4(r0, r1, r2, r3, addr) \
    asm volatile("ldmatrix.sync.aligned.m8n8.x4.shared.b16 {%0,%1,%2,%3}, [%4];" \
                 : "=r"(r0), "=r"(r1), "=r"(r2), "=r"(r3) : "r"(addr))

#define CP16(dst, src) \
    asm volatile("cp.async.cg.shared.global [%0], [%1], 16;" :: "r"(dst), "l"(src))

__device__ __forceinline__ void mma_f16(float* d, const uint32_t* a, const uint32_t* b) {
    asm volatile(
        "mma.sync.aligned.m16n8k16.row.col.f32.f16.f16.f32 "
        "{%0,%1,%2,%3},{%4,%5,%6,%7},{%8,%9},{%0,%1,%2,%3};"
        : "+f"(d[0]), "+f"(d[1]), "+f"(d[2]), "+f"(d[3])
        : "r"(a[0]), "r"(a[1]), "r"(a[2]), "r"(a[3]), "r"(b[0]), "r"(b[1]));
}

// ===================== init =====================
__global__ void init_kernel(float* __restrict__ out) {
    int i = blockIdx.x * blockDim.x + threadIdx.x;
    if (i < NN) g_deg[i] = 0;
    if (i < 512) out[i] = 0.0f;
}

// ===================== CSR build =====================
__global__ void count_kernel(const int* __restrict__ ei) {
    int e = blockIdx.x * blockDim.x + threadIdx.x;
    if (e < NE) atomicAdd(&g_deg[ei[NE + e]], 1);
}

__global__ void scan_kernel() {
    __shared__ int wsum[32];
    int tid = threadIdx.x, lane = tid & 31, w = tid >> 5;
    int carry = 0;
    for (int base = 0; base < NN; base += 1024) {
        int idx = base + tid;
        int v = (idx < NN) ? g_deg[idx] : 0;
        int x = v;
        #pragma unroll
        for (int o = 1; o < 32; o <<= 1) {
            int t = __shfl_up_sync(0xffffffffu, x, o);
            if (lane >= o) x += t;
        }
        if (lane == 31) wsum[w] = x;
        __syncthreads();
        if (w == 0) {
            int s = wsum[lane];
            #pragma unroll
            for (int o = 1; o < 32; o <<= 1) {
                int t = __shfl_up_sync(0xffffffffu, s, o);
                if (lane >= o) s += t;
            }
            wsum[lane] = s;
        }
        __syncthreads();
        int excl = x - v + (w ? wsum[w - 1] : 0) + carry;
        if (idx < NN) { g_off[idx] = excl; g_cur[idx] = excl; }
        int total = wsum[31];
        __syncthreads();
        carry += total;
    }
    if (tid == 0) g_off[NN] = carry;
}

__global__ void scatter_kernel(const int* __restrict__ ei) {
    int e = blockIdx.x * blockDim.x + threadIdx.x;
    if (e < NE) {
        int d = ei[NE + e];
        int p = atomicAdd(&g_cur[d], 1);
        g_srcSorted[p] = ei[e];
    }
}

// ===================== weight convert: W[K,256] -> [N=256,K] fp16 ==============
__global__ void conv_w_kernel(const float* __restrict__ Wq, const float* __restrict__ Wk,
                              const float* __restrict__ Wv, const float* __restrict__ Ws,
                              const float* __restrict__ Wa, const float* __restrict__ Wb) {
    int mat = blockIdx.y;
    int K = (mat < 4) ? 1024 : 256;
    size_t off = (mat < 4) ? (size_t)mat * WBIG : (size_t)4 * WBIG + (size_t)(mat - 4) * WSML;
    const float* W = (mat == 0) ? Wq : (mat == 1) ? Wk : (mat == 2) ? Wv :
                     (mat == 3) ? Ws : (mat == 4) ? Wa : Wb;
    int idx = blockIdx.x * blockDim.x + threadIdx.x;
    if (idx < 256 * K) {
        int n = idx / K, k = idx % K;
        g_WH[off + idx] = __float2half_rn(W[(size_t)k * 256 + n]);
    }
}

// ===================== x convert: fp32 -> fp16 (vectorized) ====================
__global__ void conv_x_kernel(const float* __restrict__ X) {
    size_t i = ((size_t)blockIdx.x * blockDim.x + threadIdx.x) * 8;
    if (i < (size_t)NN * LIN) {
        float4 a = *(const float4*)(X + i);
        float4 b = *(const float4*)(X + i + 4);
        uint4 pk;
        __half2 h0 = __floats2half2_rn(a.x, a.y);
        __half2 h1 = __floats2half2_rn(a.z, a.w);
        __half2 h2 = __floats2half2_rn(b.x, b.y);
        __half2 h3 = __floats2half2_rn(b.z, b.w);
        pk.x = *(uint32_t*)&h0; pk.y = *(uint32_t*)&h1;
        pk.z = *(uint32_t*)&h2; pk.w = *(uint32_t*)&h3;
        *(uint4*)(g_Xh + i) = pk;
    }
}

// ===================== HMMA GEMM (fp16, pure cp.async, 4-stage) ================
// Block: 96(M) x 256(N), BK=32, 384 threads = 12 warps of 32x64.
// SMEM stage: A[96][40] fp16, B[256][40] fp16 (pad 40 elems/row)
#define AH_OFF 0
#define BH_OFF 7680
#define STAGE  28160
#define NSTAGE 4
#define GEMM_SMEM (NSTAGE * STAGE)
#define BM 96

template <int KDIM>
__global__ __launch_bounds__(384, 1)
void mma_gemm(const __half* __restrict__ Ah, int M, int matBase,
              const float* __restrict__ bias0, const float* __restrict__ bias1,
              const float* __restrict__ bias2, const float* __restrict__ bias3) {
    extern __shared__ char sm[];
    uint32_t smb = smem_u32(sm);
    int tid = threadIdx.x;
    int wid = tid >> 5;
    int lane = tid & 31;

    int mat = blockIdx.x;
    int m0 = blockIdx.y * BM;
    size_t wOff = (KDIM == 1024) ? (size_t)mat * WBIG
                                 : (size_t)4 * WBIG + (size_t)mat * WSML;
    const float* bias = (mat == 0) ? bias0 : (mat == 1) ? bias1 : (mat == 2) ? bias2 : bias3;
    // matBase==0 -> all outputs fp16 (Qh,Kh,Vh,Sh); matBase==4 -> fp32 (TA,TB)
    __half* Oh = (mat == 0) ? g_Qh : (mat == 1) ? g_Kh : (mat == 2) ? g_Vh : g_Sh;
    float*  Of = (mat == 0) ? g_TA : g_TB;
    bool half_out = (matBase == 0);

    uint64_t gW, gA;
    {
        const __half* pw = g_WH + wOff;
        asm("cvta.to.global.u64 %0, %1;" : "=l"(gW) : "l"(pw));
        int rowA = m0 + (tid >> 2);
        if (rowA >= M) rowA = M - 1;
        const __half* pa = Ah + (size_t)rowA * KDIM + (tid & 3) * 8;
        asm("cvta.to.global.u64 %0, %1;" : "=l"(gA) : "l"(pa));
    }
    uint32_t aDst = (uint32_t)(tid >> 2) * 80u + (uint32_t)(tid & 3) * 16u;

    // warp tiling: wm in {0,32,64}, wn in {0,64,128,192}
    int wm = (wid >> 2) * 32;
    int wn = (wid & 3) * 64;
    uint32_t a_row = (uint32_t)(wm + (lane & 7) + (lane & 8));
    uint32_t a_col = (uint32_t)((lane & 16) >> 1);
    uint32_t b_row = (uint32_t)(wn + ((lane & 16) >> 1) + (lane & 7));
    uint32_t b_col = (uint32_t)(lane & 8);

    float c[2][8][4];
    #pragma unroll
    for (int i = 0; i < 2; i++)
        #pragma unroll
        for (int j = 0; j < 8; j++)
            #pragma unroll
            for (int u = 0; u < 4; u++) c[i][j][u] = 0.0f;

    constexpr int T = KDIM / 32;

    // ---- issue A+B cp.async for chunk t into stage t&3 ----
    auto issue = [&](int t) {
        uint32_t db = smb + (uint32_t)((t & 3) * STAGE);
        uint64_t koff = (uint64_t)t * 64;  // 32 halfs = 64 bytes
        CP16(db + AH_OFF + aDst, gA + koff);
        for (int i = tid; i < 1024; i += 384) {
            int row = i >> 2, quad = i & 3;
            uint32_t d = db + BH_OFF + (uint32_t)row * 80u + (uint32_t)quad * 16u;
            CP16(d, gW + (uint64_t)row * (KDIM * 2) + koff + quad * 16);
        }
        asm volatile("cp.async.commit_group;" ::: "memory");
    };

    // ---- prologue: fill 3 stages ----
    issue(0);
    issue(1);
    issue(2);

    for (int t = 0; t < T; ++t) {
        if (t + 3 < T)      { asm volatile("cp.async.wait_group 2;" ::: "memory"); }
        else if (t + 2 < T) { asm volatile("cp.async.wait_group 1;" ::: "memory"); }
        else                { asm volatile("cp.async.wait_group 0;" ::: "memory"); }
        __syncthreads();

        if (t + 3 < T) issue(t + 3);

        uint32_t sb = smb + (uint32_t)((t & 3) * STAGE);
        #pragma unroll
        for (int ks = 0; ks < 2; ks++) {
            uint32_t ahr[2][4];
            #pragma unroll
            for (int i = 0; i < 2; i++) {
                uint32_t off = (a_row + i * 16) * 80u + (ks * 16 + a_col) * 2u;
                LDM_X4(ahr[i][0], ahr[i][1], ahr[i][2], ahr[i][3], sb + AH_OFF + off);
            }
            uint32_t bhr[8][2];
            #pragma unroll
            for (int p = 0; p < 4; p++) {
                uint32_t off = (b_row + p * 16) * 80u + (ks * 16 + b_col) * 2u;
                LDM_X4(bhr[2 * p][0], bhr[2 * p][1], bhr[2 * p + 1][0], bhr[2 * p + 1][1],
                       sb + BH_OFF + off);
            }
            #pragma unroll
            for (int i = 0; i < 2; i++)
                #pragma unroll
                for (int j = 0; j < 8; j++) mma_f16(c[i][j], ahr[i], bhr[j]);
        }
    }

    // ---- epilogue: bias + store ----
    #pragma unroll
    for (int i = 0; i < 2; i++) {
        int r0 = m0 + wm + i * 16 + (lane >> 2);
        int r1 = r0 + 8;
        #pragma unroll
        for (int j = 0; j < 8; j++) {
            int cc = wn + j * 8 + (lane & 3) * 2;
            float bx = bias[cc], by = bias[cc + 1];
            if (half_out) {
                if (r0 < M)
                    *(__half2*)(Oh + (size_t)r0 * 256 + cc) =
                        __floats2half2_rn(c[i][j][0] + bx, c[i][j][1] + by);
                if (r1 < M)
                    *(__half2*)(Oh + (size_t)r1 * 256 + cc) =
                        __floats2half2_rn(c[i][j][2] + bx, c[i][j][3] + by);
            } else {
                if (r0 < M) {
                    float2 v = make_float2(c[i][j][0] + bx, c[i][j][1] + by);
                    *(float2*)(Of + (size_t)r0 * 256 + cc) = v;
                }
                if (r1 < M) {
                    float2 v = make_float2(c[i][j][2] + bx, c[i][j][3] + by);
                    *(float2*)(Of + (size_t)r1 * 256 + cc) = v;
                }
            }
        }
    }
}

// ===================== fused edge softmax + aggregation + residual + gelu ======
__global__ __launch_bounds__(256)
void attn_kernel(float* __restrict__ hOut) {
    int warp = (blockIdx.x * blockDim.x + threadIdx.x) >> 5;
    int lane = threadIdx.x & 31;
    if (warp >= NN) return;
    int d = warp;

    float q[8];
    {
        uint4 qq = *(const uint4*)(g_Qh + (size_t)d * 256 + lane * 8);
        float2 a0 = __half22float2(*(__half2*)&qq.x);
        float2 a1 = __half22float2(*(__half2*)&qq.y);
        float2 a2 = __half22float2(*(__half2*)&qq.z);
        float2 a3 = __half22float2(*(__half2*)&qq.w);
        q[0] = a0.x; q[1] = a0.y; q[2] = a1.x; q[3] = a1.y;
        q[4] = a2.x; q[5] = a2.y; q[6] = a3.x; q[7] = a3.y;
    }
    int e0 = g_off[d], e1 = g_off[d + 1];

    float amax = -INFINITY;
    for (int e = e0; e < e1; ++e) {
        int s = g_srcSorted[e];
        uint4 kk = *(const uint4*)(g_Kh + (size_t)s * 256 + lane * 8);
        float2 k0 = __half22float2(*(__half2*)&kk.x);
        float2 k1 = __half22float2(*(__half2*)&kk.y);
        float2 k2 = __half22float2(*(__half2*)&kk.z);
        float2 k3 = __half22float2(*(__half2*)&kk.w);
        float dot = q[0] * k0.x + q[1] * k0.y + q[2] * k1.x + q[3] * k1.y
                  + q[4] * k2.x + q[5] * k2.y + q[6] * k3.x + q[7] * k3.y;
        #pragma unroll
        for (int o = 16; o; o >>= 1) dot += __shfl_xor_sync(0xffffffffu, dot, o);
        dot *= 0.0625f;
        g_alpha[e] = dot;
        amax = fmaxf(amax, dot);
    }

    float den = 0.0f;
    float acc[8] = {0, 0, 0, 0, 0, 0, 0, 0};
    for (int e = e0; e < e1; ++e) {
        float w = expf(g_alpha[e] - amax);
        den += w;
        int s = g_srcSorted[e];
        uint4 vv = *(const uint4*)(g_Vh + (size_t)s * 256 + lane * 8);
        float2 v0 = __half22float2(*(__half2*)&vv.x);
        float2 v1 = __half22float2(*(__half2*)&vv.y);
        float2 v2 = __half22float2(*(__half2*)&vv.z);
        float2 v3 = __half22float2(*(__half2*)&vv.w);
        acc[0] += w * v0.x; acc[1] += w * v0.y;
        acc[2] += w * v1.x; acc[3] += w * v1.y;
        acc[4] += w * v2.x; acc[5] += w * v2.y;
        acc[6] += w * v3.x; acc[7] += w * v3.y;
    }
    float inv = 1.0f / (den + 1e-16f);

    float sv[8];
    {
        uint4 ss = *(const uint4*)(g_Sh + (size_t)d * 256 + lane * 8);
        float2 a0 = __half22float2(*(__half2*)&ss.x);
        float2 a1 = __half22float2(*(__half2*)&ss.y);
        float2 a2 = __half22float2(*(__half2*)&ss.z);
        float2 a3 = __half22float2(*(__half2*)&ss.w);
        sv[0] = a0.x; sv[1] = a0.y; sv[2] = a1.x; sv[3] = a1.y;
        sv[4] = a2.x; sv[5] = a2.y; sv[6] = a3.x; sv[7] = a3.y;
    }
    float hv[8];
    #pragma unroll
    for (int u = 0; u < 8; u++) hv[u] = gelu_exact(acc[u] * inv + sv[u]);

    float4* Hr = (float4*)(hOut + (size_t)d * 256);
    Hr[2 * lane]     = make_float4(hv[0], hv[1], hv[2], hv[3]);
    Hr[2 * lane + 1] = make_float4(hv[4], hv[5], hv[6], hv[7]);

    __half2 p0 = __floats2half2_rn(hv[0], hv[1]);
    __half2 p1 = __floats2half2_rn(hv[2], hv[3]);
    __half2 p2 = __floats2half2_rn(hv[4], hv[5]);
    __half2 p3 = __floats2half2_rn(hv[6], hv[7]);
    uint4 pk;
    pk.x = *(uint32_t*)&p0; pk.y = *(uint32_t*)&p1;
    pk.z = *(uint32_t*)&p2; pk.w = *(uint32_t*)&p3;
    *(uint4*)(g_Hh + (size_t)d * 256 + lane * 8) = pk;
}

// ===================== gate + scores =====================
__global__ __launch_bounds__(256)
void act_scores_kernel(const float* __restrict__ Wc, const float* __restrict__ bc) {
    int warp = (blockIdx.x * blockDim.x + threadIdx.x) >> 5;
    int lane = threadIdx.x & 31;
    if (warp >= NN) return;
    int n = warp;

    const float4* Ar = (const float4*)(g_TA + (size_t)n * 256);
    const float4* Br = (const float4*)(g_TB + (size_t)n * 256);
    float s0 = 0.0f, s1 = 0.0f;
    #pragma unroll
    for (int part = 0; part < 2; part++) {
        int idx = 2 * lane + part;
        float4 av = Ar[idx], bv = Br[idx];
        float aa[4] = {av.x, av.y, av.z, av.w};
        float bb[4] = {bv.x, bv.y, bv.z, bv.w};
        int jbase = idx * 4;
        #pragma unroll
        for (int u = 0; u < 4; u++) {
            float a = tanhf(aa[u]);
            float b = 1.0f / (1.0f + expf(-bb[u]));
            float g = a * b;
            s0 += g * Wc[(jbase + u) * 2 + 0];
            s1 += g * Wc[(jbase + u) * 2 + 1];
        }
    }
    #pragma unroll
    for (int o = 16; o; o >>= 1) {
        s0 += __shfl_xor_sync(0xffffffffu, s0, o);
        s1 += __shfl_xor_sync(0xffffffffu, s1, o);
    }
    if (lane == 0) {
        g_scores[2 * n + 0] = s0 + bc[0];
        g_scores[2 * n + 1] = s1 + bc[1];
    }
}

// ===================== column softmax stats (one block per column) =============
__global__ void softmax_stats_kernel() {
    __shared__ float sh[1024];
    int tid = threadIdx.x;
    int col = blockIdx.x;
    float m = -INFINITY;
    for (int i = tid; i < NN; i += 1024)
        m = fmaxf(m, g_scores[2 * i + col]);
    sh[tid] = m; __syncthreads();
    for (int o = 512; o; o >>= 1) { if (tid < o) sh[tid] = fmaxf(sh[tid], sh[tid + o]); __syncthreads(); }
    float cm = sh[0]; __syncthreads();

    float s = 0.0f;
    for (int i = tid; i < NN; i += 1024)
        s += expf(g_scores[2 * i + col] - cm);
    sh[tid] = s; __syncthreads();
    for (int o = 512; o; o >>= 1) { if (tid < o) sh[tid] += sh[tid + o]; __syncthreads(); }
    if (tid == 0) {
        g_cmax[col] = cm;
        g_csum[col] = sh[0];
    }
}

// ===================== attn output, A, y = attn.T @ h =====================
__global__ __launch_bounds__(256)
void output_kernel(const int* __restrict__ label,
                   const float* __restrict__ h,
                   float* __restrict__ out) {
    int t = threadIdx.x;
    float cm0 = g_cmax[0], cm1 = g_cmax[1];
    float is0 = 1.0f / g_csum[0], is1 = 1.0f / g_csum[1];
    int lbl = *label;
    float y0 = 0.0f, y1 = 0.0f;
    for (int n = blockIdx.x; n < NN; n += gridDim.x) {
        float sc0 = g_scores[2 * n], sc1 = g_scores[2 * n + 1];
        float a0 = expf(sc0 - cm0) * is0;
        float a1 = expf(sc1 - cm1) * is1;
        if (t == 0) out[512 + n] = (lbl == 0) ? a0 : a1;
        float hv = h[(size_t)n * 256 + t];
        y0 += a0 * hv;
        y1 += a1 * hv;
    }
    atomicAdd(&out[t], y0);
    atomicAdd(&out[256 + t], y1);
}

// ===================== stream/event resources (created at load) ================
static cudaStream_t g_s2 = 0;
static cudaEvent_t  g_e0 = 0, g_e1 = 0;
namespace {
struct StreamInit {
    StreamInit() {
        cudaStreamCreateWithFlags(&g_s2, cudaStreamNonBlocking);
        cudaEventCreateWithFlags(&g_e0, cudaEventDisableTiming);
        cudaEventCreateWithFlags(&g_e1, cudaEventDisableTiming);
    }
};
static StreamInit s_streamInit;
}

// ===================== launch =====================
extern "C" void kernel_launch(void* const* d_in, const int* in_sizes, int n_in,
                              void* d_out, int out_size) {
    const float* x  = (const float*)d_in[0];
    const float* Wq = (const float*)d_in[1];  const float* bq = (const float*)d_in[2];
    const float* Wk = (const float*)d_in[3];  const float* bk = (const float*)d_in[4];
    const float* Wv = (const float*)d_in[5];  const float* bv = (const float*)d_in[6];
    const float* Ws = (const float*)d_in[7];  const float* bs = (const float*)d_in[8];
    const float* Wa = (const float*)d_in[9];  const float* ba = (const float*)d_in[10];
    const float* Wb = (const float*)d_in[11]; const float* bb = (const float*)d_in[12];
    const float* Wc = (const float*)d_in[13]; const float* bc = (const float*)d_in[14];
    const int*   ei = (const int*)d_in[15];
    const int*   lb = (const int*)d_in[16];

    float* out  = (float*)d_out;
    float* hOut = out + 512 + NN;

    cudaFuncSetAttribute(mma_gemm<LIN>, cudaFuncAttributeMaxDynamicSharedMemorySize, GEMM_SMEM);
    cudaFuncSetAttribute(mma_gemm<DH>,  cudaFuncAttributeMaxDynamicSharedMemorySize, GEMM_SMEM);

    // ---- fork: CSR chain on side stream, conv+GEMM1 on main stream ----
    cudaEventRecord(g_e0, 0);
    cudaStreamWaitEvent(g_s2, g_e0, 0);

    init_kernel<<<(NN + 255) / 256, 256, 0, g_s2>>>(out);
    count_kernel<<<(NE + 255) / 256, 256, 0, g_s2>>>(ei);
    scan_kernel<<<1, 1024, 0, g_s2>>>();
    scatter_kernel<<<(NE + 255) / 256, 256, 0, g_s2>>>(ei);
    cudaEventRecord(g_e1, g_s2);

    conv_w_kernel<<<dim3((256 * 1024 + 255) / 256, 6), 256>>>(Wq, Wk, Wv, Ws, Wa, Wb);
    conv_x_kernel<<<((NN * (size_t)LIN / 8) + 255) / 256, 256>>>(x);

    // Q|K|V|S = x @ [Wq Wk Wv Ws] + biases  (all fp16 outputs)
    {
        __half* xh;
        cudaGetSymbolAddress((void**)&xh, g_Xh);
        mma_gemm<LIN><<<dim3(4, (NN + BM - 1) / BM), 384, GEMM_SMEM>>>(
            xh, NN, 0, bq, bk, bv, bs);
    }

    // ---- join: attn needs CSR + GEMM1 ----
    cudaStreamWaitEvent(0, g_e1, 0);

    attn_kernel<<<(NN * 32 + 255) / 256, 256>>>(hOut);

    // TA|TB = h @ [Wa Wb] + biases
    {
        __half* hh;
        cudaGetSymbolAddress((void**)&hh, g_Hh);
        mma_gemm<DH><<<dim3(2, (NN + BM - 1) / BM), 384, GEMM_SMEM>>>(
            hh, NN, 4, ba, bb, ba, ba);
    }

    act_scores_kernel<<<(NN * 32 + 255) / 256, 256>>>(Wc, bc);
    softmax_stats_kernel<<<2, 1024>>>();
    output_kernel<<<512, 256>>>(lb, hOut, out);
}